// round 4
// baseline (speedup 1.0000x reference)
#include <cuda_runtime.h>
#include <math.h>
#include <stdint.h>

#define BATCH 32
#define QLEN 300
#define BQ (BATCH*QLEN)        // 9600
#define D 256
#define NH 8
#define HD 32
#define S_TOT 8400
#define SP 12
#define FF 1024
#define LN_EPS 1e-5f

// ---------------- scratch (static device globals; no dynamic alloc) ----------
__device__ float g_hq[BQ*D];
__device__ float g_q[BQ*D];
__device__ float g_k[BQ*D];
__device__ float g_v[BQ*D];
__device__ float g_attn[BQ*D];
__device__ float g_res[BQ*D];
__device__ float g_offs[BQ*192];
__device__ float g_awl[BQ*96];
__device__ float g_aw[BQ*96];
__device__ float g_ca[BQ*D];
__device__ float g_cat[BQ*512];
__device__ float g_gates[BQ*512];
__device__ float g_h2[BQ*D];
__device__ float g_ffn1[BQ*FF];
__device__ float g_ffn2[BQ*D];

#define MMA_TF32(C, A0, A1, A2, A3, B0, B1)                                  \
    asm volatile(                                                            \
        "mma.sync.aligned.m16n8k8.row.col.f32.tf32.tf32.f32 "                \
        "{%0,%1,%2,%3}, {%4,%5,%6,%7}, {%8,%9}, {%0,%1,%2,%3};"              \
        : "+f"((C)[0]), "+f"((C)[1]), "+f"((C)[2]), "+f"((C)[3])             \
        : "r"(A0), "r"(A1), "r"(A2), "r"(A3), "r"(B0), "r"(B1))

__device__ __forceinline__ uint32_t fbits(float f) { return __float_as_uint(f); }

// ---------------- elementwise ------------------------------------------------
__global__ void add_kernel(const float* __restrict__ a, const float* __restrict__ b,
                           float* __restrict__ o, int n) {
    int i = blockIdx.x * blockDim.x + threadIdx.x;
    if (i < n) o[i] = a[i] + b[i];
}

__global__ void concat_kernel(const float* __restrict__ a, const float* __restrict__ b,
                              float* __restrict__ o, int rows) {
    int i = blockIdx.x * blockDim.x + threadIdx.x;
    if (i >= rows * 512) return;
    int row = i >> 9;
    int c = i & 511;
    o[i] = (c < 256) ? a[row * 256 + c] : b[row * 256 + (c - 256)];
}

// ---------------- tf32 tensor-core GEMM (128x256 CTA tile, 3-stage) ----------
// C[M,N] = act((A[M,K] @ B[K,N] + bias[N]) * alpha); act 0/1/2 = none/relu/sigmoid
// 512 threads = 16 warps (2 Mrows x 8 Ncols) of 64x32 warp tiles.
#define TM 128
#define TN 256
#define TK 32
#define AS_STRIDE 36
#define BS_STRIDE 264
#define A_TILE_F (TM*AS_STRIDE)              // 4608
#define B_TILE_F (TK*BS_STRIDE)              // 8448
#define STAGE_F  (A_TILE_F + B_TILE_F)       // 13056 floats
#define NSTAGE 3
#define GEMM_SMEM_BYTES (NSTAGE*STAGE_F*4)   // 156672 B

__device__ __forceinline__ float epi(float v, float b, float alpha, int act) {
    v = (v + b) * alpha;
    if (act == 1) v = fmaxf(v, 0.f);
    else if (act == 2) v = 1.f / (1.f + __expf(-v));
    return v;
}

__global__ __launch_bounds__(512)
void tgemm(const float* __restrict__ A, const float* __restrict__ B,
           const float* __restrict__ bias, float* __restrict__ C,
           int M, int N, int K, float alpha, int act) {
    extern __shared__ float sm[];
    int t = threadIdx.x;
    int m0 = blockIdx.y * TM;
    int n0 = blockIdx.x * TN;
    int lane = t & 31, w = t >> 5;
    int gid = lane >> 2, tid4 = lane & 3;
    int wm = w >> 3, wn = w & 7;

    int arow = t >> 3;            // 0..63, +i*64
    int ac4  = (t & 7) * 4;
    int brow = t >> 6;            // 0..7, +i*8
    int bc4  = (t & 63) * 4;

    const int nk = K / TK;

    auto issue = [&](int kt) {
        float* As = sm + (kt % NSTAGE) * STAGE_F;
        float* Bs = As + A_TILE_F;
        int k0 = kt * TK;
#pragma unroll
        for (int i = 0; i < 2; i++) {
            int r = arow + i * 64;
            const float* src = A + (long)(m0 + r) * K + k0 + ac4;
            uint32_t dst = (uint32_t)__cvta_generic_to_shared(As + r * AS_STRIDE + ac4);
            asm volatile("cp.async.cg.shared.global [%0], [%1], 16;" :: "r"(dst), "l"(src));
        }
#pragma unroll
        for (int i = 0; i < 4; i++) {
            int r = brow + i * 8;
            int col = n0 + bc4;
            int sz = (col < N) ? 16 : 0;
            const float* src = B + (sz ? ((long)(k0 + r) * N + col) : 0);
            uint32_t dst = (uint32_t)__cvta_generic_to_shared(Bs + r * BS_STRIDE + bc4);
            asm volatile("cp.async.cg.shared.global [%0], [%1], 16, %2;"
                         :: "r"(dst), "l"(src), "r"(sz));
        }
        asm volatile("cp.async.commit_group;");
    };

    float c[4][4][4];
#pragma unroll
    for (int i = 0; i < 4; i++)
#pragma unroll
        for (int j = 0; j < 4; j++)
#pragma unroll
            for (int k = 0; k < 4; k++) c[i][j][k] = 0.f;

    issue(0);
    if (nk > 1) issue(1);
    for (int kt = 0; kt < nk; kt++) {
        if (kt + 2 < nk) {
            issue(kt + 2);
            asm volatile("cp.async.wait_group 2;");
        } else if (kt + 1 < nk) {
            asm volatile("cp.async.wait_group 1;");
        } else {
            asm volatile("cp.async.wait_group 0;");
        }
        __syncthreads();
        const float* As = sm + (kt % NSTAGE) * STAGE_F;
        const float* Bs = As + A_TILE_F;
#pragma unroll
        for (int kk = 0; kk < 4; kk++) {
            int ks = kk * 8;
            uint32_t a[4][4], b[4][2];
#pragma unroll
            for (int mt = 0; mt < 4; mt++) {
                int r = wm * 64 + mt * 16 + gid;
                a[mt][0] = fbits(As[r * AS_STRIDE + ks + tid4]);
                a[mt][1] = fbits(As[(r + 8) * AS_STRIDE + ks + tid4]);
                a[mt][2] = fbits(As[r * AS_STRIDE + ks + tid4 + 4]);
                a[mt][3] = fbits(As[(r + 8) * AS_STRIDE + ks + tid4 + 4]);
            }
#pragma unroll
            for (int nt = 0; nt < 4; nt++) {
                int cc = wn * 32 + nt * 8 + gid;
                b[nt][0] = fbits(Bs[(ks + tid4) * BS_STRIDE + cc]);
                b[nt][1] = fbits(Bs[(ks + tid4 + 4) * BS_STRIDE + cc]);
            }
#pragma unroll
            for (int mt = 0; mt < 4; mt++)
#pragma unroll
                for (int nt = 0; nt < 4; nt++)
                    MMA_TF32(c[mt][nt], a[mt][0], a[mt][1], a[mt][2], a[mt][3],
                             b[nt][0], b[nt][1]);
        }
        __syncthreads();
    }

#pragma unroll
    for (int mt = 0; mt < 4; mt++) {
        int r0 = m0 + wm * 64 + mt * 16 + gid;
#pragma unroll
        for (int nt = 0; nt < 4; nt++) {
            int col = n0 + wn * 32 + nt * 8 + tid4 * 2;
            if (col < N) {
                float b0 = bias[col], b1 = bias[col + 1];
                float2 v0, v1;
                v0.x = epi(c[mt][nt][0], b0, alpha, act);
                v0.y = epi(c[mt][nt][1], b1, alpha, act);
                v1.x = epi(c[mt][nt][2], b0, alpha, act);
                v1.y = epi(c[mt][nt][3], b1, alpha, act);
                *(float2*)&C[(long)r0 * N + col] = v0;
                *(float2*)&C[(long)(r0 + 8) * N + col] = v1;
            }
        }
    }
}

// ---------------- flash attention (tf32 MMA) ---------------------------------
#define AT_QS 36
#define AT_KS 36
#define AT_VS 40

__global__ __launch_bounds__(128)
void flash_attn(const float* __restrict__ Qm, const float* __restrict__ Km,
                const float* __restrict__ Vm, float* __restrict__ O) {
    __shared__ float Qs[64 * AT_QS];
    __shared__ float Ks[64 * AT_KS];
    __shared__ float Vs[64 * AT_VS];
    int t = threadIdx.x;
    int lane = t & 31, w = t >> 5;
    int gid = lane >> 2, tid4 = lane & 3;
    int qt = blockIdx.x;
    int bh = blockIdx.y;
    int b = bh >> 3, h = bh & 7;
    long base = (long)b * QLEN * D + h * HD;

#pragma unroll
    for (int i = 0; i < 4; i++) {
        int e = t + i * 128;
        int row = e >> 3, c4 = (e & 7) * 4;
        int q = qt * 64 + row;
        float4 v = make_float4(0.f, 0.f, 0.f, 0.f);
        if (q < QLEN) v = *(const float4*)&Qm[base + (long)q * D + c4];
        *(float4*)&Qs[row * AT_QS + c4] = v;
    }
    __syncthreads();

    uint32_t aq[4][4];
    int r0 = w * 16 + gid;
#pragma unroll
    for (int k4 = 0; k4 < 4; k4++) {
        int ks = k4 * 8;
        aq[k4][0] = fbits(Qs[r0 * AT_QS + ks + tid4]);
        aq[k4][1] = fbits(Qs[(r0 + 8) * AT_QS + ks + tid4]);
        aq[k4][2] = fbits(Qs[r0 * AT_QS + ks + tid4 + 4]);
        aq[k4][3] = fbits(Qs[(r0 + 8) * AT_QS + ks + tid4 + 4]);
    }

    float m0 = -1e30f, m1 = -1e30f, l0 = 0.f, l1 = 0.f;
    float co[4][4] = {};

    for (int kt = 0; kt < 5; kt++) {
        __syncthreads();
#pragma unroll
        for (int i = 0; i < 4; i++) {
            int e = t + i * 128;
            int row = e >> 3, c4 = (e & 7) * 4;
            int kk = kt * 64 + row;
            float4 v = make_float4(0.f, 0.f, 0.f, 0.f);
            float4 u = make_float4(0.f, 0.f, 0.f, 0.f);
            if (kk < QLEN) {
                v = *(const float4*)&Km[base + (long)kk * D + c4];
                u = *(const float4*)&Vm[base + (long)kk * D + c4];
            }
            *(float4*)&Ks[row * AT_KS + c4] = v;
            *(float4*)&Vs[row * AT_VS + c4] = u;
        }
        __syncthreads();

        float cs[8][4];
#pragma unroll
        for (int nt = 0; nt < 8; nt++)
#pragma unroll
            for (int j = 0; j < 4; j++) cs[nt][j] = 0.f;
#pragma unroll
        for (int k4 = 0; k4 < 4; k4++) {
            int ks = k4 * 8;
#pragma unroll
            for (int nt = 0; nt < 8; nt++) {
                int key = nt * 8 + gid;
                uint32_t b0 = fbits(Ks[key * AT_KS + ks + tid4]);
                uint32_t b1 = fbits(Ks[key * AT_KS + ks + tid4 + 4]);
                MMA_TF32(cs[nt], aq[k4][0], aq[k4][1], aq[k4][2], aq[k4][3], b0, b1);
            }
        }

        if (kt == 4) {
#pragma unroll
            for (int nt = 0; nt < 8; nt++) {
                int col = 256 + nt * 8 + 2 * tid4;
                if (col >= QLEN)     { cs[nt][0] = -1e30f; cs[nt][2] = -1e30f; }
                if (col + 1 >= QLEN) { cs[nt][1] = -1e30f; cs[nt][3] = -1e30f; }
            }
        }

        float t0 = -1e30f, t1 = -1e30f;
#pragma unroll
        for (int nt = 0; nt < 8; nt++) {
            t0 = fmaxf(t0, fmaxf(cs[nt][0], cs[nt][1]));
            t1 = fmaxf(t1, fmaxf(cs[nt][2], cs[nt][3]));
        }
#pragma unroll
        for (int off = 1; off <= 2; off <<= 1) {
            t0 = fmaxf(t0, __shfl_xor_sync(0xffffffffu, t0, off));
            t1 = fmaxf(t1, __shfl_xor_sync(0xffffffffu, t1, off));
        }
        float nm0 = fmaxf(m0, t0), nm1 = fmaxf(m1, t1);
        float sc0 = __expf(m0 - nm0), sc1 = __expf(m1 - nm1);
        m0 = nm0; m1 = nm1;

        float s0 = 0.f, s1 = 0.f;
#pragma unroll
        for (int nt = 0; nt < 8; nt++) {
            cs[nt][0] = __expf(cs[nt][0] - nm0);
            cs[nt][1] = __expf(cs[nt][1] - nm0);
            cs[nt][2] = __expf(cs[nt][2] - nm1);
            cs[nt][3] = __expf(cs[nt][3] - nm1);
            s0 += cs[nt][0] + cs[nt][1];
            s1 += cs[nt][2] + cs[nt][3];
        }
#pragma unroll
        for (int off = 1; off <= 2; off <<= 1) {
            s0 += __shfl_xor_sync(0xffffffffu, s0, off);
            s1 += __shfl_xor_sync(0xffffffffu, s1, off);
        }
        l0 = l0 * sc0 + s0;
        l1 = l1 * sc1 + s1;
#pragma unroll
        for (int dt = 0; dt < 4; dt++) {
            co[dt][0] *= sc0; co[dt][1] *= sc0;
            co[dt][2] *= sc1; co[dt][3] *= sc1;
        }

        int L1 = (gid << 2) | (tid4 >> 1);
        int L2 = L1 + 2;
        bool odd = tid4 & 1;
#pragma unroll
        for (int kk = 0; kk < 8; kk++) {
            float p00 = __shfl_sync(0xffffffffu, cs[kk][0], L1);
            float p01 = __shfl_sync(0xffffffffu, cs[kk][1], L1);
            float p10 = __shfl_sync(0xffffffffu, cs[kk][2], L1);
            float p11 = __shfl_sync(0xffffffffu, cs[kk][3], L1);
            float q00 = __shfl_sync(0xffffffffu, cs[kk][0], L2);
            float q01 = __shfl_sync(0xffffffffu, cs[kk][1], L2);
            float q10 = __shfl_sync(0xffffffffu, cs[kk][2], L2);
            float q11 = __shfl_sync(0xffffffffu, cs[kk][3], L2);
            uint32_t a0 = fbits(odd ? p01 : p00);
            uint32_t a1 = fbits(odd ? p11 : p10);
            uint32_t a2 = fbits(odd ? q01 : q00);
            uint32_t a3 = fbits(odd ? q11 : q10);
#pragma unroll
            for (int dt = 0; dt < 4; dt++) {
                int d = dt * 8 + gid;
                uint32_t b0 = fbits(Vs[(kk * 8 + tid4) * AT_VS + d]);
                uint32_t b1 = fbits(Vs[(kk * 8 + tid4 + 4) * AT_VS + d]);
                MMA_TF32(co[dt], a0, a1, a2, a3, b0, b1);
            }
        }
    }

    float il0 = 1.f / l0, il1 = 1.f / l1;
    int q0 = qt * 64 + w * 16 + gid;
    int q1 = q0 + 8;
#pragma unroll
    for (int dt = 0; dt < 4; dt++) {
        int d = h * HD + dt * 8 + 2 * tid4;
        if (q0 < QLEN) {
            float2 v; v.x = co[dt][0] * il0; v.y = co[dt][1] * il0;
            *(float2*)&O[(long)(b * QLEN + q0) * D + d] = v;
        }
        if (q1 < QLEN) {
            float2 v; v.x = co[dt][2] * il1; v.y = co[dt][3] * il1;
            *(float2*)&O[(long)(b * QLEN + q1) * D + d] = v;
        }
    }
}

// ---------------- layernorm helpers ------------------------------------------
__device__ __forceinline__ float block_sum256(float v) {
    __shared__ float sh[8];
#pragma unroll
    for (int off = 16; off > 0; off >>= 1)
        v += __shfl_xor_sync(0xffffffffu, v, off);
    int t = threadIdx.x;
    if ((t & 31) == 0) sh[t >> 5] = v;
    __syncthreads();
    if (t == 0) {
        float s = 0.f;
        for (int i = 0; i < 8; i++) s += sh[i];
        sh[0] = s;
    }
    __syncthreads();
    float r = sh[0];
    __syncthreads();
    return r;
}

__device__ __forceinline__ void ln_write(float x, const float* w, const float* bb,
                                         float* O, int row) {
    int t = threadIdx.x;
    float mean = block_sum256(x) * (1.f / D);
    float d_ = x - mean;
    float var = block_sum256(d_ * d_) * (1.f / D);
    O[(long)row * D + t] = d_ * rsqrtf(var + LN_EPS) * w[t] + bb[t];
}

__global__ void ln_add(const float* __restrict__ A, const float* __restrict__ Bv,
                       const float* __restrict__ w, const float* __restrict__ bb,
                       float* __restrict__ O) {
    int row = blockIdx.x, t = threadIdx.x;
    float x = A[(long)row * D + t] + Bv[(long)row * D + t];
    ln_write(x, w, bb, O, row);
}

__global__ void gate_ln(const float* __restrict__ gates, const float* __restrict__ res,
                        const float* __restrict__ ca, const float* __restrict__ w,
                        const float* __restrict__ bb, float* __restrict__ O) {
    int row = blockIdx.x, t = threadIdx.x;
    float g1 = gates[(long)row * 512 + t];
    float g2 = gates[(long)row * 512 + 256 + t];
    float x = g1 * res[(long)row * D + t] + g2 * ca[(long)row * D + t];
    ln_write(x, w, bb, O, row);
}

// ---------------- aw softmax over SP=12 --------------------------------------
__global__ void softmax12(const float* __restrict__ in, float* __restrict__ out, int rows) {
    int r = blockIdx.x * blockDim.x + threadIdx.x;
    if (r >= rows) return;
    const float* p = in + (long)r * SP;
    float* o = out + (long)r * SP;
    float mx = -1e30f;
#pragma unroll
    for (int i = 0; i < SP; i++) mx = fmaxf(mx, p[i]);
    float e[SP], s = 0.f;
#pragma unroll
    for (int i = 0; i < SP; i++) { e[i] = __expf(p[i] - mx); s += e[i]; }
    float inv = 1.f / s;
#pragma unroll
    for (int i = 0; i < SP; i++) o[i] = e[i] * inv;
}

// ---------------- deformable bilinear sampling -------------------------------
__global__ void sample_kernel(const float* __restrict__ enc, const float* __restrict__ ref,
                              const float* __restrict__ offs, const float* __restrict__ aw,
                              float* __restrict__ ca) {
    int bq = blockIdx.x;
    int b = bq / QLEN;
    int t = threadIdx.x;
    int h = t >> 5, lane = t & 31;
    const float* rp = ref + (long)bq * 4;
    float rx = rp[0], ry = rp[1], rw = rp[2], rh = rp[3];
    const float* op = offs + (long)bq * 192 + h * 24;
    const float* ap = aw + (long)bq * 96 + h * 12;
    const float* eb = enc + (long)b * S_TOT * D + h * HD + lane;
    float acc = 0.f;
#pragma unroll
    for (int p = 0; p < SP; p++) {
        int lvl = p >> 2;
        int Wl = (lvl == 0) ? 80 : (lvl == 1) ? 40 : 20;
        int Hl = Wl;
        int s0 = (lvl == 0) ? 0 : (lvl == 1) ? 6400 : 8000;
        float ox = op[p * 2], oy = op[p * 2 + 1];
        float a = ap[p];
        float gx = (rx + ox * 0.125f * rw) * (float)Wl - 0.5f;
        float gy = (ry + oy * 0.125f * rh) * (float)Hl - 0.5f;
        float x0f = floorf(gx), y0f = floorf(gy);
        float fx = gx - x0f, fy = gy - y0f;
        int x0 = (int)x0f, y0 = (int)y0f;
        int x1 = x0 + 1, y1 = y0 + 1;
        float w00 = (1.f - fx) * (1.f - fy) * a;
        float w10 = fx * (1.f - fy) * a;
        float w01 = (1.f - fx) * fy * a;
        float w11 = fx * fy * a;
        bool vx0 = (x0 >= 0) & (x0 < Wl), vx1 = (x1 >= 0) & (x1 < Wl);
        bool vy0 = (y0 >= 0) & (y0 < Hl), vy1 = (y1 >= 0) & (y1 < Hl);
        if (vx0 & vy0) acc += w00 * eb[(long)(s0 + y0 * Wl + x0) * D];
        if (vx1 & vy0) acc += w10 * eb[(long)(s0 + y0 * Wl + x1) * D];
        if (vx0 & vy1) acc += w01 * eb[(long)(s0 + y1 * Wl + x0) * D];
        if (vx1 & vy1) acc += w11 * eb[(long)(s0 + y1 * Wl + x1) * D];
    }
    ca[(long)bq * D + h * HD + lane] = acc;
}

// ---------------- host orchestration -----------------------------------------
static void launch_gemm(const float* A, const float* B, const float* bias, float* C,
                        int M, int N, int K, float alpha, int act) {
    dim3 grid((N + TN - 1) / TN, M / TM);
    tgemm<<<grid, 512, GEMM_SMEM_BYTES>>>(A, B, bias, C, M, N, K, alpha, act);
}

extern "C" void kernel_launch(void* const* d_in, const int* in_sizes, int n_in,
                              void* d_out, int out_size) {
    const float* hs    = (const float*)d_in[0];
    const float* pos   = (const float*)d_in[1];
    const float* ref   = (const float*)d_in[2];
    const float* enc   = (const float*)d_in[3];
    const float* q_w   = (const float*)d_in[4];
    const float* q_b   = (const float*)d_in[5];
    const float* k_w   = (const float*)d_in[6];
    const float* k_b   = (const float*)d_in[7];
    const float* v_w   = (const float*)d_in[8];
    const float* v_b   = (const float*)d_in[9];
    const float* o_w   = (const float*)d_in[10];
    const float* o_b   = (const float*)d_in[11];
    const float* sa_ln_w = (const float*)d_in[12];
    const float* sa_ln_b = (const float*)d_in[13];
    const float* off_w = (const float*)d_in[14];
    const float* off_b = (const float*)d_in[15];
    const float* aw_w  = (const float*)d_in[16];
    const float* aw_b  = (const float*)d_in[17];
    const float* gate_w = (const float*)d_in[18];
    const float* gate_b = (const float*)d_in[19];
    const float* gate_ln_w = (const float*)d_in[20];
    const float* gate_ln_b = (const float*)d_in[21];
    const float* fc1_w = (const float*)d_in[22];
    const float* fc1_b = (const float*)d_in[23];
    const float* fc2_w = (const float*)d_in[24];
    const float* fc2_b = (const float*)d_in[25];
    const float* fin_ln_w = (const float*)d_in[26];
    const float* fin_ln_b = (const float*)d_in[27];
    float* out = (float*)d_out;

    float *p_hq, *p_q, *p_k, *p_v, *p_attn, *p_res, *p_offs, *p_awl, *p_aw,
          *p_ca, *p_cat, *p_gates, *p_h2, *p_ffn1, *p_ffn2;
    cudaGetSymbolAddress((void**)&p_hq, g_hq);
    cudaGetSymbolAddress((void**)&p_q, g_q);
    cudaGetSymbolAddress((void**)&p_k, g_k);
    cudaGetSymbolAddress((void**)&p_v, g_v);
    cudaGetSymbolAddress((void**)&p_attn, g_attn);
    cudaGetSymbolAddress((void**)&p_res, g_res);
    cudaGetSymbolAddress((void**)&p_offs, g_offs);
    cudaGetSymbolAddress((void**)&p_awl, g_awl);
    cudaGetSymbolAddress((void**)&p_aw, g_aw);
    cudaGetSymbolAddress((void**)&p_ca, g_ca);
    cudaGetSymbolAddress((void**)&p_cat, g_cat);
    cudaGetSymbolAddress((void**)&p_gates, g_gates);
    cudaGetSymbolAddress((void**)&p_h2, g_h2);
    cudaGetSymbolAddress((void**)&p_ffn1, g_ffn1);
    cudaGetSymbolAddress((void**)&p_ffn2, g_ffn2);

    cudaFuncSetAttribute(tgemm, cudaFuncAttributeMaxDynamicSharedMemorySize,
                         GEMM_SMEM_BYTES);

    const float scaling = 0.17677669529663687f; // 32^-0.5
    dim3 blk(256);

    add_kernel<<<BQ * D / 256, blk>>>(hs, pos, p_hq, BQ * D);

    launch_gemm(p_hq, q_w, q_b, p_q, BQ, D, D, scaling, 0);
    launch_gemm(p_hq, k_w, k_b, p_k, BQ, D, D, 1.f, 0);
    launch_gemm(hs,   v_w, v_b, p_v, BQ, D, D, 1.f, 0);

    flash_attn<<<dim3(5, BATCH * NH), 128>>>(p_q, p_k, p_v, p_attn);

    launch_gemm(p_attn, o_w, o_b, p_hq, BQ, D, D, 1.f, 0);
    ln_add<<<BQ, blk>>>(hs, p_hq, sa_ln_w, sa_ln_b, p_res);

    launch_gemm(p_res, off_w, off_b, p_offs, BQ, 192, D, 1.f, 0);
    launch_gemm(p_res, aw_w, aw_b, p_awl, BQ, 96, D, 1.f, 0);
    softmax12<<<(BQ * NH + 255) / 256, blk>>>(p_awl, p_aw, BQ * NH);

    sample_kernel<<<BQ, blk>>>(enc, ref, p_offs, p_aw, p_ca);

    concat_kernel<<<BQ * 512 / 256, blk>>>(p_res, p_ca, p_cat, BQ);
    launch_gemm(p_cat, gate_w, gate_b, p_gates, BQ, 512, 512, 1.f, 2);
    gate_ln<<<BQ, blk>>>(p_gates, p_res, p_ca, gate_ln_w, gate_ln_b, p_h2);

    launch_gemm(p_h2, fc1_w, fc1_b, p_ffn1, BQ, FF, D, 1.f, 1);
    launch_gemm(p_ffn1, fc2_w, fc2_b, p_ffn2, BQ, D, FF, 1.f, 0);

    ln_add<<<BQ, blk>>>(p_h2, p_ffn2, fin_ln_w, fin_ln_b, out);
}

// round 6
// speedup vs baseline: 1.2929x; 1.2929x over previous
#include <cuda_runtime.h>
#include <cuda_fp16.h>
#include <math.h>
#include <stdint.h>

#define BATCH 32
#define QLEN 300
#define BQ (BATCH*QLEN)        // 9600
#define D 256
#define NH 8
#define HD 32
#define S_TOT 8400
#define SP 12
#define FF 1024
#define LN_EPS 1e-5f

// ---------------- scratch (static device globals; no dynamic alloc) ----------
__device__ __half g_hq16[BQ*D];
__device__ __half g_hs16[BQ*D];
__device__ float  g_qk[BQ*512];          // fused q|k output
__device__ float  g_v[BQ*D];
__device__ __half g_attn16[BQ*D];
__device__ float  g_res[BQ*D];
__device__ __half g_res16[BQ*D];
__device__ float  g_offaw[BQ*288];       // fused offs|aw-logits
__device__ float  g_aw[BQ*96];
__device__ float  g_ca[BQ*D];
__device__ __half g_cat16[BQ*512];
__device__ float  g_gates[BQ*512];
__device__ float  g_h2[BQ*D];
__device__ __half g_h216[BQ*D];
__device__ __half g_ffn1[BQ*FF];
__device__ float  g_ffn2[BQ*D];
__device__ __half g_wt16[1122304];       // transposed fp16 weights [N,K]
__device__ float  g_qkb[512];
__device__ float  g_oab[288];

// offsets into g_wt16 (elements)
#define WT_QK   0           // [512,256] (q rows then k rows)
#define WT_V    131072
#define WT_O    196608
#define WT_OA   262144      // [288,256] (off rows then aw rows)
#define WT_GATE 335872
#define WT_FC1  598016
#define WT_FC2  860160

__device__ __forceinline__ uint32_t f2tf(float f) {
    uint32_t r; asm("cvt.rna.tf32.f32 %0, %1;" : "=r"(r) : "f"(f)); return r;
}

#define MMA_TF32(C, A0, A1, A2, A3, B0, B1)                                  \
    asm volatile(                                                            \
        "mma.sync.aligned.m16n8k8.row.col.f32.tf32.tf32.f32 "                \
        "{%0,%1,%2,%3}, {%4,%5,%6,%7}, {%8,%9}, {%0,%1,%2,%3};"              \
        : "+f"((C)[0]), "+f"((C)[1]), "+f"((C)[2]), "+f"((C)[3])             \
        : "r"(A0), "r"(A1), "r"(A2), "r"(A3), "r"(B0), "r"(B1))

#define MMA_F16(C, A0, A1, A2, A3, B0, B1)                                   \
    asm volatile(                                                            \
        "mma.sync.aligned.m16n8k16.row.col.f32.f16.f16.f32 "                 \
        "{%0,%1,%2,%3}, {%4,%5,%6,%7}, {%8,%9}, {%0,%1,%2,%3};"              \
        : "+f"((C)[0]), "+f"((C)[1]), "+f"((C)[2]), "+f"((C)[3])             \
        : "r"(A0), "r"(A1), "r"(A2), "r"(A3), "r"(B0), "r"(B1))

// ---------------- prep: hq16 = half(hs+pos), hs16 = half(hs) -----------------
__global__ void prep_kernel(const float* __restrict__ hs, const float* __restrict__ pos,
                            __half* __restrict__ hq16, __half* __restrict__ hs16, int n) {
    int i = blockIdx.x * blockDim.x + threadIdx.x;
    if (i < n) {
        float h = hs[i];
        hq16[i] = __float2half_rn(h + pos[i]);
        hs16[i] = __float2half_rn(h);
    }
}

__global__ void concat16_kernel(const float* __restrict__ a, const float* __restrict__ b,
                                __half* __restrict__ o, int rows) {
    int i = blockIdx.x * blockDim.x + threadIdx.x;
    if (i >= rows * 512) return;
    int row = i >> 9;
    int c = i & 511;
    o[i] = __float2half_rn((c < 256) ? a[row * 256 + c] : b[row * 256 + (c - 256)]);
}

// ---------------- weight transpose+convert: in[K,N] fp32 -> out[N,K] fp16 ----
__global__ void transpose_wh(const float* __restrict__ in, __half* __restrict__ out,
                             int K, int N) {
    __shared__ float tile[32][33];
    int bx = blockIdx.x * 32;  // N
    int by = blockIdx.y * 32;  // K
    int tx = threadIdx.x, ty = threadIdx.y;
#pragma unroll
    for (int i = 0; i < 32; i += 8)
        tile[ty + i][tx] = in[(long)(by + ty + i) * N + bx + tx];
    __syncthreads();
#pragma unroll
    for (int i = 0; i < 32; i += 8)
        out[(long)(bx + ty + i) * K + by + tx] = __float2half_rn(tile[tx][ty + i]);
}

// ---------------- fp16 tensor-core GEMM --------------------------------------
// C = act(A[M,K]fp16 @ Bt[N,K]fp16^T + bias[N]); outmode bit0: fp32 C32, bit1: fp16 C16
// CTA 128x128x32, 256 thr (8 warps 2x4, warp tile 64x32), m16n8k16.
#define TM 128
#define TN 128
#define TK 32
#define HS 40                       // halves per smem row (stride)
#define TILE_H (128*HS)             // 5120 halves per operand
#define STAGE_H (2*TILE_H)

__device__ __forceinline__ float epi(float v, float b, int act) {
    v = v + b;
    if (act == 1) v = fmaxf(v, 0.f);
    else if (act == 2) v = 1.f / (1.f + __expf(-v));
    return v;
}

__global__ __launch_bounds__(256)
void tgemm_h(const __half* __restrict__ A, const __half* __restrict__ Bt,
             const float* __restrict__ bias, float* __restrict__ C32,
             __half* __restrict__ C16, int M, int N, int K, int act, int outmode) {
    __shared__ __half sm[2][STAGE_H];
    int t = threadIdx.x;
    int m0 = blockIdx.y * TM;
    int n0 = blockIdx.x * TN;
    int lane = t & 31, w = t >> 5;
    int gid = lane >> 2, tid4 = lane & 3;
    int wm = w >> 2, wn = w & 3;

    int lrow = t >> 2;              // 0..63, +64
    int lc8  = (t & 3) * 8;         // half offset within row

    const int nk = K / TK;

    auto issue = [&](int kt) {
        __half* As = sm[kt & 1];
        __half* Bs = As + TILE_H;
        int k0 = kt * TK;
#pragma unroll
        for (int i = 0; i < 2; i++) {
            int r = lrow + i * 64;
            const __half* src = A + (long)(m0 + r) * K + k0 + lc8;
            uint32_t dst = (uint32_t)__cvta_generic_to_shared(As + r * HS + lc8);
            asm volatile("cp.async.cg.shared.global [%0], [%1], 16;" :: "r"(dst), "l"(src));
        }
#pragma unroll
        for (int i = 0; i < 2; i++) {
            int r = lrow + i * 64;
            int n = n0 + r;
            int sz = (n < N) ? 16 : 0;
            const __half* src = Bt + (sz ? ((long)n * K + k0 + lc8) : 0);
            uint32_t dst = (uint32_t)__cvta_generic_to_shared(Bs + r * HS + lc8);
            asm volatile("cp.async.cg.shared.global [%0], [%1], 16, %2;"
                         :: "r"(dst), "l"(src), "r"(sz));
        }
        asm volatile("cp.async.commit_group;");
    };

    float c[4][4][4];
#pragma unroll
    for (int i = 0; i < 4; i++)
#pragma unroll
        for (int j = 0; j < 4; j++)
#pragma unroll
            for (int k = 0; k < 4; k++) c[i][j][k] = 0.f;

    issue(0);
    for (int kt = 0; kt < nk; kt++) {
        if (kt + 1 < nk) {
            issue(kt + 1);
            asm volatile("cp.async.wait_group 1;");
        } else {
            asm volatile("cp.async.wait_group 0;");
        }
        __syncthreads();
        const __half* As = sm[kt & 1];
        const __half* Bs = As + TILE_H;
#pragma unroll
        for (int g = 0; g < 2; g++) {       // two k16 groups per K32 chunk
            int ko = g * 16 + tid4 * 2;
            uint32_t a[4][4], b[4][2];
#pragma unroll
            for (int mt = 0; mt < 4; mt++) {
                int r = wm * 64 + mt * 16 + gid;
                a[mt][0] = *(const uint32_t*)&As[r * HS + ko];
                a[mt][1] = *(const uint32_t*)&As[(r + 8) * HS + ko];
                a[mt][2] = *(const uint32_t*)&As[r * HS + ko + 8];
                a[mt][3] = *(const uint32_t*)&As[(r + 8) * HS + ko + 8];
            }
#pragma unroll
            for (int nt = 0; nt < 4; nt++) {
                int n = wn * 32 + nt * 8 + gid;
                b[nt][0] = *(const uint32_t*)&Bs[n * HS + ko];
                b[nt][1] = *(const uint32_t*)&Bs[n * HS + ko + 8];
            }
#pragma unroll
            for (int mt = 0; mt < 4; mt++)
#pragma unroll
                for (int nt = 0; nt < 4; nt++)
                    MMA_F16(c[mt][nt], a[mt][0], a[mt][1], a[mt][2], a[mt][3],
                            b[nt][0], b[nt][1]);
        }
        __syncthreads();
    }

#pragma unroll
    for (int mt = 0; mt < 4; mt++) {
        int r0 = m0 + wm * 64 + mt * 16 + gid;
#pragma unroll
        for (int nt = 0; nt < 4; nt++) {
            int col = n0 + wn * 32 + nt * 8 + tid4 * 2;
            if (col < N) {
                float b0 = bias[col], b1 = bias[col + 1];
                float v00 = epi(c[mt][nt][0], b0, act);
                float v01 = epi(c[mt][nt][1], b1, act);
                float v10 = epi(c[mt][nt][2], b0, act);
                float v11 = epi(c[mt][nt][3], b1, act);
                if (outmode & 1) {
                    float2 u0; u0.x = v00; u0.y = v01;
                    float2 u1; u1.x = v10; u1.y = v11;
                    *(float2*)&C32[(long)r0 * N + col] = u0;
                    *(float2*)&C32[(long)(r0 + 8) * N + col] = u1;
                }
                if (outmode & 2) {
                    *(__half2*)&C16[(long)r0 * N + col] = __floats2half2_rn(v00, v01);
                    *(__half2*)&C16[(long)(r0 + 8) * N + col] = __floats2half2_rn(v10, v11);
                }
            }
        }
    }
}

// ---------------- flash attention (tf32 MMA) ---------------------------------
// Q,K from fused g_qk [BQ,512] (Q cols 0..255, K cols 256..511); V [BQ,256].
// Applies softmax scaling to scores. Output fp16 [BQ,256].
#define AT_QS 36
#define AT_KS 36
#define AT_VS 40
#define SM_SCALE 0.17677669529663687f

__global__ __launch_bounds__(128)
void flash_attn(const float* __restrict__ QK, const float* __restrict__ Vm,
                __half* __restrict__ O) {
    __shared__ float Qs[64 * AT_QS];
    __shared__ float Ks[64 * AT_KS];
    __shared__ float Vs[64 * AT_VS];
    int t = threadIdx.x;
    int lane = t & 31, w = t >> 5;
    int gid = lane >> 2, tid4 = lane & 3;
    int qt = blockIdx.x;
    int bh = blockIdx.y;
    int b = bh >> 3, h = bh & 7;
    long rowbase = (long)b * QLEN;

#pragma unroll
    for (int i = 0; i < 4; i++) {
        int e = t + i * 128;
        int row = e >> 3, c4 = (e & 7) * 4;
        int q = qt * 64 + row;
        float4 v = make_float4(0.f, 0.f, 0.f, 0.f);
        if (q < QLEN) v = *(const float4*)&QK[(rowbase + q) * 512 + h * HD + c4];
        *(float4*)&Qs[row * AT_QS + c4] = v;
    }
    __syncthreads();

    uint32_t aq[4][4];
    int r0 = w * 16 + gid;
#pragma unroll
    for (int k4 = 0; k4 < 4; k4++) {
        int ks = k4 * 8;
        aq[k4][0] = f2tf(Qs[r0 * AT_QS + ks + tid4]);
        aq[k4][1] = f2tf(Qs[(r0 + 8) * AT_QS + ks + tid4]);
        aq[k4][2] = f2tf(Qs[r0 * AT_QS + ks + tid4 + 4]);
        aq[k4][3] = f2tf(Qs[(r0 + 8) * AT_QS + ks + tid4 + 4]);
    }

    float m0 = -1e30f, m1 = -1e30f, l0 = 0.f, l1 = 0.f;
    float co[4][4] = {};

    for (int kt = 0; kt < 5; kt++) {
        __syncthreads();
#pragma unroll
        for (int i = 0; i < 4; i++) {
            int e = t + i * 128;
            int row = e >> 3, c4 = (e & 7) * 4;
            int kk = kt * 64 + row;
            float4 v = make_float4(0.f, 0.f, 0.f, 0.f);
            float4 u = make_float4(0.f, 0.f, 0.f, 0.f);
            if (kk < QLEN) {
                v = *(const float4*)&QK[(rowbase + kk) * 512 + 256 + h * HD + c4];
                u = *(const float4*)&Vm[(rowbase + kk) * 256 + h * HD + c4];
            }
            *(float4*)&Ks[row * AT_KS + c4] = v;
            *(float4*)&Vs[row * AT_VS + c4] = u;
        }
        __syncthreads();

        float cs[8][4];
#pragma unroll
        for (int nt = 0; nt < 8; nt++)
#pragma unroll
            for (int j = 0; j < 4; j++) cs[nt][j] = 0.f;
#pragma unroll
        for (int k4 = 0; k4 < 4; k4++) {
            int ks = k4 * 8;
#pragma unroll
            for (int nt = 0; nt < 8; nt++) {
                int key = nt * 8 + gid;
                uint32_t b0 = f2tf(Ks[key * AT_KS + ks + tid4]);
                uint32_t b1 = f2tf(Ks[key * AT_KS + ks + tid4 + 4]);
                MMA_TF32(cs[nt], aq[k4][0], aq[k4][1], aq[k4][2], aq[k4][3], b0, b1);
            }
        }

#pragma unroll
        for (int nt = 0; nt < 8; nt++)
#pragma unroll
            for (int j = 0; j < 4; j++) cs[nt][j] *= SM_SCALE;

        if (kt == 4) {
#pragma unroll
            for (int nt = 0; nt < 8; nt++) {
                int col = 256 + nt * 8 + 2 * tid4;
                if (col >= QLEN)     { cs[nt][0] = -1e30f; cs[nt][2] = -1e30f; }
                if (col + 1 >= QLEN) { cs[nt][1] = -1e30f; cs[nt][3] = -1e30f; }
            }
        }

        float t0 = -1e30f, t1 = -1e30f;
#pragma unroll
        for (int nt = 0; nt < 8; nt++) {
            t0 = fmaxf(t0, fmaxf(cs[nt][0], cs[nt][1]));
            t1 = fmaxf(t1, fmaxf(cs[nt][2], cs[nt][3]));
        }
#pragma unroll
        for (int off = 1; off <= 2; off <<= 1) {
            t0 = fmaxf(t0, __shfl_xor_sync(0xffffffffu, t0, off));
            t1 = fmaxf(t1, __shfl_xor_sync(0xffffffffu, t1, off));
        }
        float nm0 = fmaxf(m0, t0), nm1 = fmaxf(m1, t1);
        float sc0 = __expf(m0 - nm0), sc1 = __expf(m1 - nm1);
        m0 = nm0; m1 = nm1;

        float s0 = 0.f, s1 = 0.f;
#pragma unroll
        for (int nt = 0; nt < 8; nt++) {
            cs[nt][0] = __expf(cs[nt][0] - nm0);
            cs[nt][1] = __expf(cs[nt][1] - nm0);
            cs[nt][2] = __expf(cs[nt][2] - nm1);
            cs[nt][3] = __expf(cs[nt][3] - nm1);
            s0 += cs[nt][0] + cs[nt][1];
            s1 += cs[nt][2] + cs[nt][3];
        }
#pragma unroll
        for (int off = 1; off <= 2; off <<= 1) {
            s0 += __shfl_xor_sync(0xffffffffu, s0, off);
            s1 += __shfl_xor_sync(0xffffffffu, s1, off);
        }
        l0 = l0 * sc0 + s0;
        l1 = l1 * sc1 + s1;
#pragma unroll
        for (int dt = 0; dt < 4; dt++) {
            co[dt][0] *= sc0; co[dt][1] *= sc0;
            co[dt][2] *= sc1; co[dt][3] *= sc1;
        }

        int L1 = (gid << 2) | (tid4 >> 1);
        int L2 = L1 + 2;
        bool odd = tid4 & 1;
#pragma unroll
        for (int kk = 0; kk < 8; kk++) {
            float p00 = __shfl_sync(0xffffffffu, cs[kk][0], L1);
            float p01 = __shfl_sync(0xffffffffu, cs[kk][1], L1);
            float p10 = __shfl_sync(0xffffffffu, cs[kk][2], L1);
            float p11 = __shfl_sync(0xffffffffu, cs[kk][3], L1);
            float q00 = __shfl_sync(0xffffffffu, cs[kk][0], L2);
            float q01 = __shfl_sync(0xffffffffu, cs[kk][1], L2);
            float q10 = __shfl_sync(0xffffffffu, cs[kk][2], L2);
            float q11 = __shfl_sync(0xffffffffu, cs[kk][3], L2);
            uint32_t a0 = f2tf(odd ? p01 : p00);
            uint32_t a1 = f2tf(odd ? p11 : p10);
            uint32_t a2 = f2tf(odd ? q01 : q00);
            uint32_t a3 = f2tf(odd ? q11 : q10);
#pragma unroll
            for (int dt = 0; dt < 4; dt++) {
                int d = dt * 8 + gid;
                uint32_t b0 = f2tf(Vs[(kk * 8 + tid4) * AT_VS + d]);
                uint32_t b1 = f2tf(Vs[(kk * 8 + tid4 + 4) * AT_VS + d]);
                MMA_TF32(co[dt], a0, a1, a2, a3, b0, b1);
            }
        }
    }

    float il0 = 1.f / l0, il1 = 1.f / l1;
    int q0 = qt * 64 + w * 16 + gid;
    int q1 = q0 + 8;
#pragma unroll
    for (int dt = 0; dt < 4; dt++) {
        int d = h * HD + dt * 8 + 2 * tid4;
        if (q0 < QLEN)
            *(__half2*)&O[((long)b * QLEN + q0) * D + d] =
                __floats2half2_rn(co[dt][0] * il0, co[dt][1] * il0);
        if (q1 < QLEN)
            *(__half2*)&O[((long)b * QLEN + q1) * D + d] =
                __floats2half2_rn(co[dt][2] * il1, co[dt][3] * il1);
    }
}

// ---------------- layernorm helpers ------------------------------------------
__device__ __forceinline__ float block_sum256(float v) {
    __shared__ float sh[8];
#pragma unroll
    for (int off = 16; off > 0; off >>= 1)
        v += __shfl_xor_sync(0xffffffffu, v, off);
    int t = threadIdx.x;
    if ((t & 31) == 0) sh[t >> 5] = v;
    __syncthreads();
    if (t == 0) {
        float s = 0.f;
        for (int i = 0; i < 8; i++) s += sh[i];
        sh[0] = s;
    }
    __syncthreads();
    float r = sh[0];
    __syncthreads();
    return r;
}

__device__ __forceinline__ void ln_write(float x, const float* w, const float* bb,
                                         float* O32, __half* O16, int row) {
    int t = threadIdx.x;
    float mean = block_sum256(x) * (1.f / D);
    float d_ = x - mean;
    float var = block_sum256(d_ * d_) * (1.f / D);
    float y = d_ * rsqrtf(var + LN_EPS) * w[t] + bb[t];
    O32[(long)row * D + t] = y;
    if (O16) O16[(long)row * D + t] = __float2half_rn(y);
}

__global__ void ln_add(const float* __restrict__ A, const float* __restrict__ Bv,
                       const float* __restrict__ w, const float* __restrict__ bb,
                       float* __restrict__ O32, __half* O16) {
    int row = blockIdx.x, t = threadIdx.x;
    float x = A[(long)row * D + t] + Bv[(long)row * D + t];
    ln_write(x, w, bb, O32, O16, row);
}

__global__ void gate_ln(const float* __restrict__ gates, const float* __restrict__ res,
                        const float* __restrict__ ca, const float* __restrict__ w,
                        const float* __restrict__ bb, float* __restrict__ O32,
                        __half* O16) {
    int row = blockIdx.x, t = threadIdx.x;
    float g1 = gates[(long)row * 512 + t];
    float g2 = gates[(long)row * 512 + 256 + t];
    float x = g1 * res[(long)row * D + t] + g2 * ca[(long)row * D + t];
    ln_write(x, w, bb, O32, O16, row);
}

// ---------------- aw softmax over SP=12 (reads fused offaw buffer) -----------
__global__ void softmax12(const float* __restrict__ offaw, float* __restrict__ out,
                          int rows) {
    int r = blockIdx.x * blockDim.x + threadIdx.x;
    if (r >= rows) return;
    int bq = r >> 3, h = r & 7;
    const float* p = offaw + (long)bq * 288 + 192 + h * SP;
    float* o = out + (long)r * SP;
    float mx = -1e30f;
#pragma unroll
    for (int i = 0; i < SP; i++) mx = fmaxf(mx, p[i]);
    float e[SP], s = 0.f;
#pragma unroll
    for (int i = 0; i < SP; i++) { e[i] = __expf(p[i] - mx); s += e[i]; }
    float inv = 1.f / s;
#pragma unroll
    for (int i = 0; i < SP; i++) o[i] = e[i] * inv;
}

// ---------------- deformable bilinear sampling (branch-free) ------------------
__global__ void sample_kernel(const float* __restrict__ enc, const float* __restrict__ ref,
                              const float* __restrict__ offaw, const float* __restrict__ aw,
                              float* __restrict__ ca) {
    int bq = blockIdx.x;
    int b = bq / QLEN;
    int t = threadIdx.x;
    int h = t >> 5, lane = t & 31;
    const float* rp = ref + (long)bq * 4;
    float rx = rp[0], ry = rp[1], rw = rp[2], rh = rp[3];
    const float* op = offaw + (long)bq * 288 + h * 24;
    const float* ap = aw + (long)bq * 96 + h * 12;
    const float* eb = enc + (long)b * S_TOT * D + h * HD + lane;
    float acc = 0.f;
#pragma unroll
    for (int p = 0; p < SP; p++) {
        int lvl = p >> 2;
        int Wl = (lvl == 0) ? 80 : (lvl == 1) ? 40 : 20;
        int s0 = (lvl == 0) ? 0 : (lvl == 1) ? 6400 : 8000;
        float ox = op[p * 2], oy = op[p * 2 + 1];
        float a = ap[p];
        float gx = (rx + ox * 0.125f * rw) * (float)Wl - 0.5f;
        float gy = (ry + oy * 0.125f * rh) * (float)Wl - 0.5f;
        float x0f = floorf(gx), y0f = floorf(gy);
        float fx = gx - x0f, fy = gy - y0f;
        int x0 = (int)x0f, y0 = (int)y0f;
        int x1 = x0 + 1, y1 = y0 + 1;
        float vx0 = (x0 >= 0 && x0 < Wl) ? 1.f : 0.f;
        float vx1 = (x1 >= 0 && x1 < Wl) ? 1.f : 0.f;
        float vy0 = (y0 >= 0 && y0 < Wl) ? 1.f : 0.f;
        float vy1 = (y1 >= 0 && y1 < Wl) ? 1.f : 0.f;
        float w00 = (1.f - fx) * (1.f - fy) * a * vx0 * vy0;
        float w10 = fx * (1.f - fy) * a * vx1 * vy0;
        float w01 = (1.f - fx) * fy * a * vx0 * vy1;
        float w11 = fx * fy * a * vx1 * vy1;
        int xc0 = min(max(x0, 0), Wl - 1), xc1 = min(max(x1, 0), Wl - 1);
        int yc0 = min(max(y0, 0), Wl - 1), yc1 = min(max(y1, 0), Wl - 1);
        float e00 = eb[(long)(s0 + yc0 * Wl + xc0) * D];
        float e10 = eb[(long)(s0 + yc0 * Wl + xc1) * D];
        float e01 = eb[(long)(s0 + yc1 * Wl + xc0) * D];
        float e11 = eb[(long)(s0 + yc1 * Wl + xc1) * D];
        acc += w00 * e00 + w10 * e10 + w01 * e01 + w11 * e11;
    }
    ca[(long)bq * D + h * HD + lane] = acc;
}

// ---------------- host orchestration -----------------------------------------
static void launch_gemm(const __half* A, const __half* Bt, const float* bias,
                        float* C32, __half* C16, int M, int N, int K,
                        int act, int outmode) {
    dim3 grid((N + TN - 1) / TN, M / TM);
    tgemm_h<<<grid, 256>>>(A, Bt, bias, C32, C16, M, N, K, act, outmode);
}

extern "C" void kernel_launch(void* const* d_in, const int* in_sizes, int n_in,
                              void* d_out, int out_size) {
    const float* hs    = (const float*)d_in[0];
    const float* pos   = (const float*)d_in[1];
    const float* ref   = (const float*)d_in[2];
    const float* enc   = (const float*)d_in[3];
    const float* q_w   = (const float*)d_in[4];
    const float* q_b   = (const float*)d_in[5];
    const float* k_w   = (const float*)d_in[6];
    const float* k_b   = (const float*)d_in[7];
    const float* v_w   = (const float*)d_in[8];
    const float* v_b   = (const float*)d_in[9];
    const float* o_w   = (const float*)d_in[10];
    const float* o_b   = (const float*)d_in[11];
    const float* sa_ln_w = (const float*)d_in[12];
    const float* sa_ln_b = (const float*)d_in[13];
    const float* off_w = (const float*)d_in[14];
    const float* off_b = (const float*)d_in[15];
    const float* aw_w  = (const float*)d_in[16];
    const float* aw_b  = (const float*)d_in[17];
    const float* gate_w = (const float*)d_in[18];
    const float* gate_b = (const float*)d_in[19];
    const float* gate_ln_w = (const float*)d_in[20];
    const float* gate_ln_b = (const float*)d_in[21];
    const float* fc1_w = (const float*)d_in[22];
    const float* fc1_b = (const float*)d_in[23];
    const float* fc2_w = (const float*)d_in[24];
    const float* fc2_b = (const float*)d_in[25];
    const float* fin_ln_w = (const float*)d_in[26];
    const float* fin_ln_b = (const float*)d_in[27];
    float* out = (float*)d_out;

    __half *p_hq16, *p_hs16, *p_attn16, *p_res16, *p_cat16, *p_h216, *p_ffn1, *p_wt;
    float *p_qk, *p_v, *p_res, *p_offaw, *p_aw, *p_ca, *p_gates, *p_h2, *p_ffn2,
          *p_qkb, *p_oab;
    cudaGetSymbolAddress((void**)&p_hq16, g_hq16);
    cudaGetSymbolAddress((void**)&p_hs16, g_hs16);
    cudaGetSymbolAddress((void**)&p_qk, g_qk);
    cudaGetSymbolAddress((void**)&p_v, g_v);
    cudaGetSymbolAddress((void**)&p_attn16, g_attn16);
    cudaGetSymbolAddress((void**)&p_res, g_res);
    cudaGetSymbolAddress((void**)&p_res16, g_res16);
    cudaGetSymbolAddress((void**)&p_offaw, g_offaw);
    cudaGetSymbolAddress((void**)&p_aw, g_aw);
    cudaGetSymbolAddress((void**)&p_ca, g_ca);
    cudaGetSymbolAddress((void**)&p_cat16, g_cat16);
    cudaGetSymbolAddress((void**)&p_gates, g_gates);
    cudaGetSymbolAddress((void**)&p_h2, g_h2);
    cudaGetSymbolAddress((void**)&p_h216, g_h216);
    cudaGetSymbolAddress((void**)&p_ffn1, g_ffn1);
    cudaGetSymbolAddress((void**)&p_ffn2, g_ffn2);
    cudaGetSymbolAddress((void**)&p_wt, g_wt16);
    cudaGetSymbolAddress((void**)&p_qkb, g_qkb);
    cudaGetSymbolAddress((void**)&p_oab, g_oab);

    dim3 blk(256);
    dim3 tb(32, 8);

    // weights -> [N,K] fp16 (qk and off/aw packed adjacently)
    transpose_wh<<<dim3(8,  8), tb>>>(q_w,    p_wt + WT_QK,          256, 256);
    transpose_wh<<<dim3(8,  8), tb>>>(k_w,    p_wt + WT_QK + 65536,  256, 256);
    transpose_wh<<<dim3(8,  8), tb>>>(v_w,    p_wt + WT_V,           256, 256);
    transpose_wh<<<dim3(8,  8), tb>>>(o_w,    p_wt + WT_O,           256, 256);
    transpose_wh<<<dim3(6,  8), tb>>>(off_w,  p_wt + WT_OA,          256, 192);
    transpose_wh<<<dim3(3,  8), tb>>>(aw_w,   p_wt + WT_OA + 49152,  256, 96);
    transpose_wh<<<dim3(16, 16), tb>>>(gate_w, p_wt + WT_GATE,       512, 512);
    transpose_wh<<<dim3(32, 8), tb>>>(fc1_w,  p_wt + WT_FC1,         256, 1024);
    transpose_wh<<<dim3(8, 32), tb>>>(fc2_w,  p_wt + WT_FC2,         1024, 256);

    // fused biases
    cudaMemcpyAsync(p_qkb,       q_b,  256 * 4, cudaMemcpyDeviceToDevice);
    cudaMemcpyAsync(p_qkb + 256, k_b,  256 * 4, cudaMemcpyDeviceToDevice);
    cudaMemcpyAsync(p_oab,       off_b, 192 * 4, cudaMemcpyDeviceToDevice);
    cudaMemcpyAsync(p_oab + 192, aw_b,  96 * 4, cudaMemcpyDeviceToDevice);

    prep_kernel<<<BQ * D / 256, blk>>>(hs, pos, p_hq16, p_hs16, BQ * D);

    // fused q|k projection, v projection
    launch_gemm(p_hq16, p_wt + WT_QK, p_qkb, p_qk, nullptr, BQ, 512, D, 0, 1);
    launch_gemm(p_hs16, p_wt + WT_V,  v_b,   p_v,  nullptr, BQ, 256, D, 0, 1);

    flash_attn<<<dim3(5, BATCH * NH), 128>>>(p_qk, p_v, p_attn16);

    // o projection (reuse g_qk as fp32 scratch for o-proj output)
    launch_gemm(p_attn16, p_wt + WT_O, o_b, p_qk, nullptr, BQ, 256, D, 0, 1);
    ln_add<<<BQ, blk>>>(hs, p_qk, sa_ln_w, sa_ln_b, p_res, p_res16);

    // fused off|aw projection
    launch_gemm(p_res16, p_wt + WT_OA, p_oab, p_offaw, nullptr, BQ, 288, D, 0, 1);
    softmax12<<<(BQ * NH + 255) / 256, blk>>>(p_offaw, p_aw, BQ * NH);

    sample_kernel<<<BQ, blk>>>(enc, ref, p_offaw, p_aw, p_ca);

    concat16_kernel<<<BQ * 512 / 256, blk>>>(p_res, p_ca, p_cat16, BQ);
    launch_gemm(p_cat16, p_wt + WT_GATE, gate_b, p_gates, nullptr, BQ, 512, 512, 2, 1);
    gate_ln<<<BQ, blk>>>(p_gates, p_res, p_ca, gate_ln_w, gate_ln_b, p_h2, p_h216);

    launch_gemm(p_h216, p_wt + WT_FC1, fc1_b, nullptr, p_ffn1, BQ, FF, D, 1, 2);
    launch_gemm(p_ffn1, p_wt + WT_FC2, fc2_b, p_ffn2, nullptr, BQ, 256, FF, 0, 1);

    ln_add<<<BQ, blk>>>(p_h2, p_ffn2, fin_ln_w, fin_ln_b, out, nullptr);
}

// round 7
// speedup vs baseline: 1.3357x; 1.0331x over previous
#include <cuda_runtime.h>
#include <cuda_fp16.h>
#include <math.h>
#include <stdint.h>

#define BATCH 32
#define QLEN 300
#define BQ (BATCH*QLEN)        // 9600
#define D 256
#define NH 8
#define HD 32
#define S_TOT 8400
#define SP 12
#define FF 1024
#define LN_EPS 1e-5f

// ---------------- scratch (static device globals; no dynamic alloc) ----------
__device__ __half g_hq16[BQ*D];
__device__ __half g_hs16[BQ*D];
__device__ float  g_qk[BQ*512];          // fused q|k output; reused as o-proj scratch
__device__ float  g_v[BQ*D];
__device__ __half g_attn16[BQ*D];
__device__ float  g_res[BQ*D];
__device__ float  g_offaw[BQ*288];       // fused offs|aw-logits
__device__ float  g_ca[BQ*D];
__device__ __half g_cat16[BQ*512];       // [res16 | ca16]
__device__ float  g_gates[BQ*512];
__device__ float  g_h2[BQ*D];
__device__ __half g_h216[BQ*D];
__device__ __half g_ffn1[BQ*FF];
__device__ float  g_ffn2[BQ*D];
__device__ __half g_wt16[1122304];       // transposed fp16 weights [N,K]
__device__ float  g_qkb[512];
__device__ float  g_oab[288];

// offsets into g_wt16 (elements)
#define WT_QK   0
#define WT_V    131072
#define WT_O    196608
#define WT_OA   262144
#define WT_GATE 335872
#define WT_FC1  598016
#define WT_FC2  860160

__device__ __forceinline__ uint32_t f2tf(float f) {
    uint32_t r; asm("cvt.rna.tf32.f32 %0, %1;" : "=r"(r) : "f"(f)); return r;
}

#define MMA_TF32(C, A0, A1, A2, A3, B0, B1)                                  \
    asm volatile(                                                            \
        "mma.sync.aligned.m16n8k8.row.col.f32.tf32.tf32.f32 "                \
        "{%0,%1,%2,%3}, {%4,%5,%6,%7}, {%8,%9}, {%0,%1,%2,%3};"              \
        : "+f"((C)[0]), "+f"((C)[1]), "+f"((C)[2]), "+f"((C)[3])             \
        : "r"(A0), "r"(A1), "r"(A2), "r"(A3), "r"(B0), "r"(B1))

#define MMA_F16(C, A0, A1, A2, A3, B0, B1)                                   \
    asm volatile(                                                            \
        "mma.sync.aligned.m16n8k16.row.col.f32.f16.f16.f32 "                 \
        "{%0,%1,%2,%3}, {%4,%5,%6,%7}, {%8,%9}, {%0,%1,%2,%3};"              \
        : "+f"((C)[0]), "+f"((C)[1]), "+f"((C)[2]), "+f"((C)[3])             \
        : "r"(A0), "r"(A1), "r"(A2), "r"(A3), "r"(B0), "r"(B1))

// ---------------- prep --------------------------------------------------------
__global__ void prep_kernel(const float* __restrict__ hs, const float* __restrict__ pos,
                            __half* __restrict__ hq16, __half* __restrict__ hs16, int n) {
    int i = blockIdx.x * blockDim.x + threadIdx.x;
    if (i < n) {
        float h = hs[i];
        hq16[i] = __float2half_rn(h + pos[i]);
        hs16[i] = __float2half_rn(h);
    }
}

__global__ void bias_fuse(const float* __restrict__ qb, const float* __restrict__ kb,
                          const float* __restrict__ ob, const float* __restrict__ ab,
                          float* __restrict__ qkb, float* __restrict__ oab) {
    int i = blockIdx.x * blockDim.x + threadIdx.x;
    if (i < 256) qkb[i] = qb[i];
    else if (i < 512) qkb[i] = kb[i - 256];
    else if (i < 704) oab[i - 512] = ob[i - 512];
    else if (i < 800) oab[i - 512] = ab[i - 704];
}

// ---------------- fused weight transpose: 9 matrices, one launch --------------
struct TWArgs { const float* src[9]; };

__global__ void transpose_all(TWArgs a, __half* __restrict__ out) {
    static const int base[10] = {0, 64, 128, 192, 256, 304, 328, 584, 840, 1096};
    static const int Ks[9]   = {256, 256, 256, 256, 256, 256, 512, 256, 1024};
    static const int Ns[9]   = {256, 256, 256, 256, 192, 96, 512, 1024, 256};
    static const int offs[9] = {WT_QK, WT_QK + 65536, WT_V, WT_O, WT_OA,
                                WT_OA + 49152, WT_GATE, WT_FC1, WT_FC2};
    __shared__ float tile[32][33];
    int bid = blockIdx.x;
    int m = 0;
    while (bid >= base[m + 1]) m++;
    int lt = bid - base[m];
    int K = Ks[m], N = Ns[m];
    int ntx = N >> 5;
    int bx = (lt % ntx) * 32;   // N
    int by = (lt / ntx) * 32;   // K
    const float* in = a.src[m];
    __half* o = out + offs[m];
    int tx = threadIdx.x, ty = threadIdx.y;
#pragma unroll
    for (int i = 0; i < 32; i += 8)
        tile[ty + i][tx] = in[(long)(by + ty + i) * N + bx + tx];
    __syncthreads();
#pragma unroll
    for (int i = 0; i < 32; i += 8)
        o[(long)(bx + ty + i) * K + by + tx] = __float2half_rn(tile[tx][ty + i]);
}

// ---------------- fp16 tensor-core GEMM --------------------------------------
// C = act(A[M,K]fp16(lda) @ Bt[N,K]fp16^T + bias[N]); outmode bit0 fp32, bit1 fp16
#define TM 128
#define TN 128
#define TK 32
#define HS 40
#define TILE_H (128*HS)
#define STAGE_H (2*TILE_H)

__device__ __forceinline__ float epi(float v, float b, int act) {
    v = v + b;
    if (act == 1) v = fmaxf(v, 0.f);
    else if (act == 2) v = 1.f / (1.f + __expf(-v));
    return v;
}

__global__ __launch_bounds__(256)
void tgemm_h(const __half* __restrict__ A, const __half* __restrict__ Bt,
             const float* __restrict__ bias, float* __restrict__ C32,
             __half* __restrict__ C16, int M, int N, int K, int lda,
             int act, int outmode) {
    __shared__ __half sm[2][STAGE_H];
    int t = threadIdx.x;
    int m0 = blockIdx.y * TM;
    int n0 = blockIdx.x * TN;
    int lane = t & 31, w = t >> 5;
    int gid = lane >> 2, tid4 = lane & 3;
    int wm = w >> 2, wn = w & 3;

    int lrow = t >> 2;
    int lc8  = (t & 3) * 8;

    const int nk = K / TK;

    auto issue = [&](int kt) {
        __half* As = sm[kt & 1];
        __half* Bs = As + TILE_H;
        int k0 = kt * TK;
#pragma unroll
        for (int i = 0; i < 2; i++) {
            int r = lrow + i * 64;
            const __half* src = A + (long)(m0 + r) * lda + k0 + lc8;
            uint32_t dst = (uint32_t)__cvta_generic_to_shared(As + r * HS + lc8);
            asm volatile("cp.async.cg.shared.global [%0], [%1], 16;" :: "r"(dst), "l"(src));
        }
#pragma unroll
        for (int i = 0; i < 2; i++) {
            int r = lrow + i * 64;
            int n = n0 + r;
            int sz = (n < N) ? 16 : 0;
            const __half* src = Bt + (sz ? ((long)n * K + k0 + lc8) : 0);
            uint32_t dst = (uint32_t)__cvta_generic_to_shared(Bs + r * HS + lc8);
            asm volatile("cp.async.cg.shared.global [%0], [%1], 16, %2;"
                         :: "r"(dst), "l"(src), "r"(sz));
        }
        asm volatile("cp.async.commit_group;");
    };

    float c[4][4][4];
#pragma unroll
    for (int i = 0; i < 4; i++)
#pragma unroll
        for (int j = 0; j < 4; j++)
#pragma unroll
            for (int k = 0; k < 4; k++) c[i][j][k] = 0.f;

    issue(0);
    for (int kt = 0; kt < nk; kt++) {
        if (kt + 1 < nk) {
            issue(kt + 1);
            asm volatile("cp.async.wait_group 1;");
        } else {
            asm volatile("cp.async.wait_group 0;");
        }
        __syncthreads();
        const __half* As = sm[kt & 1];
        const __half* Bs = As + TILE_H;
#pragma unroll
        for (int g = 0; g < 2; g++) {
            int ko = g * 16 + tid4 * 2;
            uint32_t a[4][4], b[4][2];
#pragma unroll
            for (int mt = 0; mt < 4; mt++) {
                int r = wm * 64 + mt * 16 + gid;
                a[mt][0] = *(const uint32_t*)&As[r * HS + ko];
                a[mt][1] = *(const uint32_t*)&As[(r + 8) * HS + ko];
                a[mt][2] = *(const uint32_t*)&As[r * HS + ko + 8];
                a[mt][3] = *(const uint32_t*)&As[(r + 8) * HS + ko + 8];
            }
#pragma unroll
            for (int nt = 0; nt < 4; nt++) {
                int n = wn * 32 + nt * 8 + gid;
                b[nt][0] = *(const uint32_t*)&Bs[n * HS + ko];
                b[nt][1] = *(const uint32_t*)&Bs[n * HS + ko + 8];
            }
#pragma unroll
            for (int mt = 0; mt < 4; mt++)
#pragma unroll
                for (int nt = 0; nt < 4; nt++)
                    MMA_F16(c[mt][nt], a[mt][0], a[mt][1], a[mt][2], a[mt][3],
                            b[nt][0], b[nt][1]);
        }
        __syncthreads();
    }

#pragma unroll
    for (int mt = 0; mt < 4; mt++) {
        int r0 = m0 + wm * 64 + mt * 16 + gid;
#pragma unroll
        for (int nt = 0; nt < 4; nt++) {
            int col = n0 + wn * 32 + nt * 8 + tid4 * 2;
            if (col < N) {
                float b0 = bias[col], b1 = bias[col + 1];
                float v00 = epi(c[mt][nt][0], b0, act);
                float v01 = epi(c[mt][nt][1], b1, act);
                float v10 = epi(c[mt][nt][2], b0, act);
                float v11 = epi(c[mt][nt][3], b1, act);
                if (outmode & 1) {
                    float2 u0; u0.x = v00; u0.y = v01;
                    float2 u1; u1.x = v10; u1.y = v11;
                    *(float2*)&C32[(long)r0 * N + col] = u0;
                    *(float2*)&C32[(long)(r0 + 8) * N + col] = u1;
                }
                if (outmode & 2) {
                    *(__half2*)&C16[(long)r0 * N + col] = __floats2half2_rn(v00, v01);
                    *(__half2*)&C16[(long)(r0 + 8) * N + col] = __floats2half2_rn(v10, v11);
                }
            }
        }
    }
}

// ---------------- flash attention (tf32 MMA) ---------------------------------
#define AT_QS 36
#define AT_KS 36
#define AT_VS 40
#define SM_SCALE 0.17677669529663687f

__global__ __launch_bounds__(128)
void flash_attn(const float* __restrict__ QK, const float* __restrict__ Vm,
                __half* __restrict__ O) {
    __shared__ float Qs[64 * AT_QS];
    __shared__ float Ks[64 * AT_KS];
    __shared__ float Vs[64 * AT_VS];
    int t = threadIdx.x;
    int lane = t & 31, w = t >> 5;
    int gid = lane >> 2, tid4 = lane & 3;
    int qt = blockIdx.x;
    int bh = blockIdx.y;
    int b = bh >> 3, h = bh & 7;
    long rowbase = (long)b * QLEN;

#pragma unroll
    for (int i = 0; i < 4; i++) {
        int e = t + i * 128;
        int row = e >> 3, c4 = (e & 7) * 4;
        int q = qt * 64 + row;
        float4 v = make_float4(0.f, 0.f, 0.f, 0.f);
        if (q < QLEN) v = *(const float4*)&QK[(rowbase + q) * 512 + h * HD + c4];
        *(float4*)&Qs[row * AT_QS + c4] = v;
    }
    __syncthreads();

    uint32_t aq[4][4];
    int r0 = w * 16 + gid;
#pragma unroll
    for (int k4 = 0; k4 < 4; k4++) {
        int ks = k4 * 8;
        aq[k4][0] = f2tf(Qs[r0 * AT_QS + ks + tid4]);
        aq[k4][1] = f2tf(Qs[(r0 + 8) * AT_QS + ks + tid4]);
        aq[k4][2] = f2tf(Qs[r0 * AT_QS + ks + tid4 + 4]);
        aq[k4][3] = f2tf(Qs[(r0 + 8) * AT_QS + ks + tid4 + 4]);
    }

    float m0 = -1e30f, m1 = -1e30f, l0 = 0.f, l1 = 0.f;
    float co[4][4] = {};

    for (int kt = 0; kt < 5; kt++) {
        __syncthreads();
#pragma unroll
        for (int i = 0; i < 4; i++) {
            int e = t + i * 128;
            int row = e >> 3, c4 = (e & 7) * 4;
            int kk = kt * 64 + row;
            float4 v = make_float4(0.f, 0.f, 0.f, 0.f);
            float4 u = make_float4(0.f, 0.f, 0.f, 0.f);
            if (kk < QLEN) {
                v = *(const float4*)&QK[(rowbase + kk) * 512 + 256 + h * HD + c4];
                u = *(const float4*)&Vm[(rowbase + kk) * 256 + h * HD + c4];
            }
            *(float4*)&Ks[row * AT_KS + c4] = v;
            *(float4*)&Vs[row * AT_VS + c4] = u;
        }
        __syncthreads();

        float cs[8][4];
#pragma unroll
        for (int nt = 0; nt < 8; nt++)
#pragma unroll
            for (int j = 0; j < 4; j++) cs[nt][j] = 0.f;
#pragma unroll
        for (int k4 = 0; k4 < 4; k4++) {
            int ks = k4 * 8;
#pragma unroll
            for (int nt = 0; nt < 8; nt++) {
                int key = nt * 8 + gid;
                uint32_t b0 = f2tf(Ks[key * AT_KS + ks + tid4]);
                uint32_t b1 = f2tf(Ks[key * AT_KS + ks + tid4 + 4]);
                MMA_TF32(cs[nt], aq[k4][0], aq[k4][1], aq[k4][2], aq[k4][3], b0, b1);
            }
        }

#pragma unroll
        for (int nt = 0; nt < 8; nt++)
#pragma unroll
            for (int j = 0; j < 4; j++) cs[nt][j] *= SM_SCALE;

        if (kt == 4) {
#pragma unroll
            for (int nt = 0; nt < 8; nt++) {
                int col = 256 + nt * 8 + 2 * tid4;
                if (col >= QLEN)     { cs[nt][0] = -1e30f; cs[nt][2] = -1e30f; }
                if (col + 1 >= QLEN) { cs[nt][1] = -1e30f; cs[nt][3] = -1e30f; }
            }
        }

        float t0 = -1e30f, t1 = -1e30f;
#pragma unroll
        for (int nt = 0; nt < 8; nt++) {
            t0 = fmaxf(t0, fmaxf(cs[nt][0], cs[nt][1]));
            t1 = fmaxf(t1, fmaxf(cs[nt][2], cs[nt][3]));
        }
#pragma unroll
        for (int off = 1; off <= 2; off <<= 1) {
            t0 = fmaxf(t0, __shfl_xor_sync(0xffffffffu, t0, off));
            t1 = fmaxf(t1, __shfl_xor_sync(0xffffffffu, t1, off));
        }
        float nm0 = fmaxf(m0, t0), nm1 = fmaxf(m1, t1);
        float sc0 = __expf(m0 - nm0), sc1 = __expf(m1 - nm1);
        m0 = nm0; m1 = nm1;

        float s0 = 0.f, s1 = 0.f;
#pragma unroll
        for (int nt = 0; nt < 8; nt++) {
            cs[nt][0] = __expf(cs[nt][0] - nm0);
            cs[nt][1] = __expf(cs[nt][1] - nm0);
            cs[nt][2] = __expf(cs[nt][2] - nm1);
            cs[nt][3] = __expf(cs[nt][3] - nm1);
            s0 += cs[nt][0] + cs[nt][1];
            s1 += cs[nt][2] + cs[nt][3];
        }
#pragma unroll
        for (int off = 1; off <= 2; off <<= 1) {
            s0 += __shfl_xor_sync(0xffffffffu, s0, off);
            s1 += __shfl_xor_sync(0xffffffffu, s1, off);
        }
        l0 = l0 * sc0 + s0;
        l1 = l1 * sc1 + s1;
#pragma unroll
        for (int dt = 0; dt < 4; dt++) {
            co[dt][0] *= sc0; co[dt][1] *= sc0;
            co[dt][2] *= sc1; co[dt][3] *= sc1;
        }

        int L1 = (gid << 2) | (tid4 >> 1);
        int L2 = L1 + 2;
        bool odd = tid4 & 1;
#pragma unroll
        for (int kk = 0; kk < 8; kk++) {
            float p00 = __shfl_sync(0xffffffffu, cs[kk][0], L1);
            float p01 = __shfl_sync(0xffffffffu, cs[kk][1], L1);
            float p10 = __shfl_sync(0xffffffffu, cs[kk][2], L1);
            float p11 = __shfl_sync(0xffffffffu, cs[kk][3], L1);
            float q00 = __shfl_sync(0xffffffffu, cs[kk][0], L2);
            float q01 = __shfl_sync(0xffffffffu, cs[kk][1], L2);
            float q10 = __shfl_sync(0xffffffffu, cs[kk][2], L2);
            float q11 = __shfl_sync(0xffffffffu, cs[kk][3], L2);
            uint32_t a0 = f2tf(odd ? p01 : p00);
            uint32_t a1 = f2tf(odd ? p11 : p10);
            uint32_t a2 = f2tf(odd ? q01 : q00);
            uint32_t a3 = f2tf(odd ? q11 : q10);
#pragma unroll
            for (int dt = 0; dt < 4; dt++) {
                int d = dt * 8 + gid;
                uint32_t b0 = f2tf(Vs[(kk * 8 + tid4) * AT_VS + d]);
                uint32_t b1 = f2tf(Vs[(kk * 8 + tid4 + 4) * AT_VS + d]);
                MMA_TF32(co[dt], a0, a1, a2, a3, b0, b1);
            }
        }
    }

    float il0 = 1.f / l0, il1 = 1.f / l1;
    int q0 = qt * 64 + w * 16 + gid;
    int q1 = q0 + 8;
#pragma unroll
    for (int dt = 0; dt < 4; dt++) {
        int d = h * HD + dt * 8 + 2 * tid4;
        if (q0 < QLEN)
            *(__half2*)&O[((long)b * QLEN + q0) * D + d] =
                __floats2half2_rn(co[dt][0] * il0, co[dt][1] * il0);
        if (q1 < QLEN)
            *(__half2*)&O[((long)b * QLEN + q1) * D + d] =
                __floats2half2_rn(co[dt][2] * il1, co[dt][3] * il1);
    }
}

// ---------------- layernorm ----------------------------------------------------
__device__ __forceinline__ float block_sum256(float v) {
    __shared__ float sh[8];
#pragma unroll
    for (int off = 16; off > 0; off >>= 1)
        v += __shfl_xor_sync(0xffffffffu, v, off);
    int t = threadIdx.x;
    if ((t & 31) == 0) sh[t >> 5] = v;
    __syncthreads();
    if (t == 0) {
        float s = 0.f;
        for (int i = 0; i < 8; i++) s += sh[i];
        sh[0] = s;
    }
    __syncthreads();
    float r = sh[0];
    __syncthreads();
    return r;
}

// O16 written at row*stride16 + t (if O16 != null)
__device__ __forceinline__ void ln_write(float x, const float* w, const float* bb,
                                         float* O32, __half* O16, int stride16, int row) {
    int t = threadIdx.x;
    float mean = block_sum256(x) * (1.f / D);
    float d_ = x - mean;
    float var = block_sum256(d_ * d_) * (1.f / D);
    float y = d_ * rsqrtf(var + LN_EPS) * w[t] + bb[t];
    O32[(long)row * D + t] = y;
    if (O16) O16[(long)row * stride16 + t] = __float2half_rn(y);
}

__global__ void ln_add(const float* __restrict__ A, const float* __restrict__ Bv,
                       const float* __restrict__ w, const float* __restrict__ bb,
                       float* __restrict__ O32, __half* O16, int stride16) {
    int row = blockIdx.x, t = threadIdx.x;
    float x = A[(long)row * D + t] + Bv[(long)row * D + t];
    ln_write(x, w, bb, O32, O16, stride16, row);
}

__global__ void gate_ln(const float* __restrict__ gates, const float* __restrict__ res,
                        const float* __restrict__ ca, const float* __restrict__ w,
                        const float* __restrict__ bb, float* __restrict__ O32,
                        __half* O16) {
    int row = blockIdx.x, t = threadIdx.x;
    float g1 = gates[(long)row * 512 + t];
    float g2 = gates[(long)row * 512 + 256 + t];
    float x = g1 * res[(long)row * D + t] + g2 * ca[(long)row * D + t];
    ln_write(x, w, bb, O32, O16, 256, row);
}

// ---------------- deformable sampling + fused softmax -------------------------
__global__ void sample_kernel(const float* __restrict__ enc, const float* __restrict__ ref,
                              const float* __restrict__ offaw, float* __restrict__ ca,
                              __half* __restrict__ cat16) {
    int bq = blockIdx.x;
    int b = bq / QLEN;
    int t = threadIdx.x;
    int h = t >> 5, lane = t & 31;
    const float* rp = ref + (long)bq * 4;
    float rx = rp[0], ry = rp[1], rw = rp[2], rh = rp[3];
    const float* op = offaw + (long)bq * 288 + h * 24;
    const float* lp = offaw + (long)bq * 288 + 192 + h * SP;
    const float* eb = enc + (long)b * S_TOT * D + h * HD + lane;

    // softmax over 12 logits (redundant per lane; loads broadcast within warp)
    float lg[SP];
    float mx = -1e30f;
#pragma unroll
    for (int i = 0; i < SP; i++) { lg[i] = lp[i]; mx = fmaxf(mx, lg[i]); }
    float ssum = 0.f;
#pragma unroll
    for (int i = 0; i < SP; i++) { lg[i] = __expf(lg[i] - mx); ssum += lg[i]; }
    float inv = 1.f / ssum;

    float acc = 0.f;
#pragma unroll
    for (int p = 0; p < SP; p++) {
        int lvl = p >> 2;
        int Wl = (lvl == 0) ? 80 : (lvl == 1) ? 40 : 20;
        int s0 = (lvl == 0) ? 0 : (lvl == 1) ? 6400 : 8000;
        float ox = op[p * 2], oy = op[p * 2 + 1];
        float a = lg[p] * inv;
        float gx = (rx + ox * 0.125f * rw) * (float)Wl - 0.5f;
        float gy = (ry + oy * 0.125f * rh) * (float)Wl - 0.5f;
        float x0f = floorf(gx), y0f = floorf(gy);
        float fx = gx - x0f, fy = gy - y0f;
        int x0 = (int)x0f, y0 = (int)y0f;
        int x1 = x0 + 1, y1 = y0 + 1;
        float vx0 = (x0 >= 0 && x0 < Wl) ? 1.f : 0.f;
        float vx1 = (x1 >= 0 && x1 < Wl) ? 1.f : 0.f;
        float vy0 = (y0 >= 0 && y0 < Wl) ? 1.f : 0.f;
        float vy1 = (y1 >= 0 && y1 < Wl) ? 1.f : 0.f;
        float w00 = (1.f - fx) * (1.f - fy) * a * vx0 * vy0;
        float w10 = fx * (1.f - fy) * a * vx1 * vy0;
        float w01 = (1.f - fx) * fy * a * vx0 * vy1;
        float w11 = fx * fy * a * vx1 * vy1;
        int xc0 = min(max(x0, 0), Wl - 1), xc1 = min(max(x1, 0), Wl - 1);
        int yc0 = min(max(y0, 0), Wl - 1), yc1 = min(max(y1, 0), Wl - 1);
        float e00 = eb[(long)(s0 + yc0 * Wl + xc0) * D];
        float e10 = eb[(long)(s0 + yc0 * Wl + xc1) * D];
        float e01 = eb[(long)(s0 + yc1 * Wl + xc0) * D];
        float e11 = eb[(long)(s0 + yc1 * Wl + xc1) * D];
        acc += w00 * e00 + w10 * e10 + w01 * e01 + w11 * e11;
    }
    ca[(long)bq * D + h * HD + lane] = acc;
    cat16[(long)bq * 512 + 256 + h * HD + lane] = __float2half_rn(acc);
}

// ---------------- host orchestration -----------------------------------------
static void launch_gemm(const __half* A, const __half* Bt, const float* bias,
                        float* C32, __half* C16, int M, int N, int K, int lda,
                        int act, int outmode) {
    dim3 grid((N + TN - 1) / TN, M / TM);
    tgemm_h<<<grid, 256>>>(A, Bt, bias, C32, C16, M, N, K, lda, act, outmode);
}

extern "C" void kernel_launch(void* const* d_in, const int* in_sizes, int n_in,
                              void* d_out, int out_size) {
    const float* hs    = (const float*)d_in[0];
    const float* pos   = (const float*)d_in[1];
    const float* ref   = (const float*)d_in[2];
    const float* enc   = (const float*)d_in[3];
    const float* q_w   = (const float*)d_in[4];
    const float* q_b   = (const float*)d_in[5];
    const float* k_w   = (const float*)d_in[6];
    const float* k_b   = (const float*)d_in[7];
    const float* v_w   = (const float*)d_in[8];
    const float* v_b   = (const float*)d_in[9];
    const float* o_w   = (const float*)d_in[10];
    const float* o_b   = (const float*)d_in[11];
    const float* sa_ln_w = (const float*)d_in[12];
    const float* sa_ln_b = (const float*)d_in[13];
    const float* off_w = (const float*)d_in[14];
    const float* off_b = (const float*)d_in[15];
    const float* aw_w  = (const float*)d_in[16];
    const float* aw_b  = (const float*)d_in[17];
    const float* gate_w = (const float*)d_in[18];
    const float* gate_b = (const float*)d_in[19];
    const float* gate_ln_w = (const float*)d_in[20];
    const float* gate_ln_b = (const float*)d_in[21];
    const float* fc1_w = (const float*)d_in[22];
    const float* fc1_b = (const float*)d_in[23];
    const float* fc2_w = (const float*)d_in[24];
    const float* fc2_b = (const float*)d_in[25];
    const float* fin_ln_w = (const float*)d_in[26];
    const float* fin_ln_b = (const float*)d_in[27];
    float* out = (float*)d_out;

    __half *p_hq16, *p_hs16, *p_attn16, *p_cat16, *p_h216, *p_ffn1, *p_wt;
    float *p_qk, *p_v, *p_res, *p_offaw, *p_ca, *p_gates, *p_h2, *p_ffn2,
          *p_qkb, *p_oab;
    cudaGetSymbolAddress((void**)&p_hq16, g_hq16);
    cudaGetSymbolAddress((void**)&p_hs16, g_hs16);
    cudaGetSymbolAddress((void**)&p_qk, g_qk);
    cudaGetSymbolAddress((void**)&p_v, g_v);
    cudaGetSymbolAddress((void**)&p_attn16, g_attn16);
    cudaGetSymbolAddress((void**)&p_res, g_res);
    cudaGetSymbolAddress((void**)&p_offaw, g_offaw);
    cudaGetSymbolAddress((void**)&p_ca, g_ca);
    cudaGetSymbolAddress((void**)&p_cat16, g_cat16);
    cudaGetSymbolAddress((void**)&p_gates, g_gates);
    cudaGetSymbolAddress((void**)&p_h2, g_h2);
    cudaGetSymbolAddress((void**)&p_h216, g_h216);
    cudaGetSymbolAddress((void**)&p_ffn1, g_ffn1);
    cudaGetSymbolAddress((void**)&p_ffn2, g_ffn2);
    cudaGetSymbolAddress((void**)&p_wt, g_wt16);
    cudaGetSymbolAddress((void**)&p_qkb, g_qkb);
    cudaGetSymbolAddress((void**)&p_oab, g_oab);

    dim3 blk(256);

    // fused weight transpose (1 launch) + bias fuse (1 launch)
    TWArgs tw;
    tw.src[0] = q_w;  tw.src[1] = k_w;   tw.src[2] = v_w;  tw.src[3] = o_w;
    tw.src[4] = off_w; tw.src[5] = aw_w; tw.src[6] = gate_w;
    tw.src[7] = fc1_w; tw.src[8] = fc2_w;
    transpose_all<<<1096, dim3(32, 8)>>>(tw, p_wt);
    bias_fuse<<<4, 256>>>(q_b, k_b, off_b, aw_b, p_qkb, p_oab);

    prep_kernel<<<BQ * D / 256, blk>>>(hs, pos, p_hq16, p_hs16, BQ * D);

    launch_gemm(p_hq16, p_wt + WT_QK, p_qkb, p_qk, nullptr, BQ, 512, D, 256, 0, 1);
    launch_gemm(p_hs16, p_wt + WT_V,  v_b,   p_v,  nullptr, BQ, 256, D, 256, 0, 1);

    flash_attn<<<dim3(5, BATCH * NH), 128>>>(p_qk, p_v, p_attn16);

    launch_gemm(p_attn16, p_wt + WT_O, o_b, p_qk, nullptr, BQ, 256, D, 256, 0, 1);
    // sa LN: fp32 -> g_res, fp16 -> cat16 cols 0..255 (stride 512)
    ln_add<<<BQ, blk>>>(hs, p_qk, sa_ln_w, sa_ln_b, p_res, p_cat16, 512);

    // fused off|aw projection; A = res16 inside cat16 (lda=512)
    launch_gemm(p_cat16, p_wt + WT_OA, p_oab, p_offaw, nullptr, BQ, 288, D, 512, 0, 1);

    // sampling (softmax fused); writes ca fp32 + cat16 cols 256..511
    sample_kernel<<<BQ, blk>>>(enc, ref, p_offaw, p_ca, p_cat16);

    launch_gemm(p_cat16, p_wt + WT_GATE, gate_b, p_gates, nullptr, BQ, 512, 512, 512, 2, 1);
    gate_ln<<<BQ, blk>>>(p_gates, p_res, p_ca, gate_ln_w, gate_ln_b, p_h2, p_h216);

    launch_gemm(p_h216, p_wt + WT_FC1, fc1_b, nullptr, p_ffn1, BQ, FF, D, 256, 1, 2);
    launch_gemm(p_ffn1, p_wt + WT_FC2, fc2_b, p_ffn2, nullptr, BQ, 256, FF, 1024, 0, 1);

    ln_add<<<BQ, blk>>>(p_h2, p_ffn2, fin_ln_w, fin_ln_b, out, nullptr, 0);
}

// round 8
// speedup vs baseline: 1.3557x; 1.0150x over previous
#include <cuda_runtime.h>
#include <cuda_fp16.h>
#include <math.h>
#include <stdint.h>

#define BATCH 32
#define QLEN 300
#define BQ (BATCH*QLEN)        // 9600
#define D 256
#define NH 8
#define HD 32
#define S_TOT 8400
#define SP 12
#define FF 1024
#define LN_EPS 1e-5f

// ---------------- scratch (static device globals; no dynamic alloc) ----------
__device__ __half g_hq16[BQ*D];
__device__ __half g_hs16[BQ*D];
__device__ float  g_qk[BQ*512];
__device__ float  g_v[BQ*D];
__device__ __half g_attn16[BQ*D];
__device__ float  g_res[BQ*D];
__device__ float  g_offaw[BQ*288];
__device__ float  g_ca[BQ*D];
__device__ __half g_cat16[BQ*512];
__device__ float  g_gates[BQ*512];
__device__ float  g_h2[BQ*D];
__device__ __half g_h216[BQ*D];
__device__ __half g_ffn1[BQ*FF];
__device__ float  g_ffn2[BQ*D];
__device__ __half g_wt16[1122304];
__device__ float  g_qkb[512];
__device__ float  g_oab[288];

#define WT_QK   0
#define WT_V    131072
#define WT_O    196608
#define WT_OA   262144
#define WT_GATE 335872
#define WT_FC1  598016
#define WT_FC2  860160

__device__ __forceinline__ uint32_t f2tf(float f) {
    uint32_t r; asm("cvt.rna.tf32.f32 %0, %1;" : "=r"(r) : "f"(f)); return r;
}

#define MMA_TF32(C, A0, A1, A2, A3, B0, B1)                                  \
    asm volatile(                                                            \
        "mma.sync.aligned.m16n8k8.row.col.f32.tf32.tf32.f32 "                \
        "{%0,%1,%2,%3}, {%4,%5,%6,%7}, {%8,%9}, {%0,%1,%2,%3};"              \
        : "+f"((C)[0]), "+f"((C)[1]), "+f"((C)[2]), "+f"((C)[3])             \
        : "r"(A0), "r"(A1), "r"(A2), "r"(A3), "r"(B0), "r"(B1))

#define MMA_F16(C, A0, A1, A2, A3, B0, B1)                                   \
    asm volatile(                                                            \
        "mma.sync.aligned.m16n8k16.row.col.f32.f16.f16.f32 "                 \
        "{%0,%1,%2,%3}, {%4,%5,%6,%7}, {%8,%9}, {%0,%1,%2,%3};"              \
        : "+f"((C)[0]), "+f"((C)[1]), "+f"((C)[2]), "+f"((C)[3])             \
        : "r"(A0), "r"(A1), "r"(A2), "r"(A3), "r"(B0), "r"(B1))

#define LDSM_X4(R, addr)                                                     \
    asm volatile("ldmatrix.sync.aligned.m8n8.x4.shared.b16 {%0,%1,%2,%3}, [%4];" \
        : "=r"((R)[0]), "=r"((R)[1]), "=r"((R)[2]), "=r"((R)[3]) : "r"(addr))

// ---------------- prep --------------------------------------------------------
__global__ void prep_kernel(const float* __restrict__ hs, const float* __restrict__ pos,
                            __half* __restrict__ hq16, __half* __restrict__ hs16, int n) {
    int i = blockIdx.x * blockDim.x + threadIdx.x;
    if (i < n) {
        float h = hs[i];
        hq16[i] = __float2half_rn(h + pos[i]);
        hs16[i] = __float2half_rn(h);
    }
}

__global__ void bias_fuse(const float* __restrict__ qb, const float* __restrict__ kb,
                          const float* __restrict__ ob, const float* __restrict__ ab,
                          float* __restrict__ qkb, float* __restrict__ oab) {
    int i = blockIdx.x * blockDim.x + threadIdx.x;
    if (i < 256) qkb[i] = qb[i];
    else if (i < 512) qkb[i] = kb[i - 256];
    else if (i < 704) oab[i - 512] = ob[i - 512];
    else if (i < 800) oab[i - 512] = ab[i - 704];
}

// ---------------- fused weight transpose --------------------------------------
struct TWArgs { const float* src[9]; };

__global__ void transpose_all(TWArgs a, __half* __restrict__ out) {
    static const int base[10] = {0, 64, 128, 192, 256, 304, 328, 584, 840, 1096};
    static const int Ks[9]   = {256, 256, 256, 256, 256, 256, 512, 256, 1024};
    static const int Ns[9]   = {256, 256, 256, 256, 192, 96, 512, 1024, 256};
    static const int offs[9] = {WT_QK, WT_QK + 65536, WT_V, WT_O, WT_OA,
                                WT_OA + 49152, WT_GATE, WT_FC1, WT_FC2};
    __shared__ float tile[32][33];
    int bid = blockIdx.x;
    int m = 0;
    while (bid >= base[m + 1]) m++;
    int lt = bid - base[m];
    int K = Ks[m], N = Ns[m];
    int ntx = N >> 5;
    int bx = (lt % ntx) * 32;
    int by = (lt / ntx) * 32;
    const float* in = a.src[m];
    __half* o = out + offs[m];
    int tx = threadIdx.x, ty = threadIdx.y;
#pragma unroll
    for (int i = 0; i < 32; i += 8)
        tile[ty + i][tx] = in[(long)(by + ty + i) * N + bx + tx];
    __syncthreads();
#pragma unroll
    for (int i = 0; i < 32; i += 8)
        o[(long)(bx + ty + i) * K + by + tx] = __float2half_rn(tile[tx][ty + i]);
}

// ---------------- fp16 tensor-core GEMM (ldmatrix + 3-stage) ------------------
#define TM 128
#define TN 128
#define TK 32
#define HS 40
#define TILE_H (128*HS)                       // 5120 halves = 10240 B per operand
#define STAGE_BYTES (2*TILE_H*2)              // 20480 B
#define B_OFF (TILE_H*2)                      // 10240 B
#define NSTAGE 3
#define GSMEM (NSTAGE*STAGE_BYTES)            // 61440 B

__device__ __forceinline__ float epi(float v, float b, int act) {
    v = v + b;
    if (act == 1) v = fmaxf(v, 0.f);
    else if (act == 2) v = 1.f / (1.f + __expf(-v));
    return v;
}

__global__ __launch_bounds__(256)
void tgemm_h(const __half* __restrict__ A, const __half* __restrict__ Bt,
             const float* __restrict__ bias, float* __restrict__ C32,
             __half* __restrict__ C16, int M, int N, int K, int lda,
             int act, int outmode) {
    extern __shared__ __half sm[];
    uint32_t smbase = (uint32_t)__cvta_generic_to_shared(sm);
    int t = threadIdx.x;
    int m0 = blockIdx.y * TM;
    int n0 = blockIdx.x * TN;
    int lane = t & 31, w = t >> 5;
    int gid = lane >> 2, tid4 = lane & 3;
    int wm = w >> 2, wn = w & 3;

    int lrow = t >> 2;
    int lc8  = (t & 3) * 8;

    const int nk = K / TK;

    // ldmatrix per-lane offsets (bytes within a stage)
    int l8 = lane & 7;
    int rplus = ((lane >> 3) & 1) * 8;   // +8 rows for matrices 1,3
    int cplus = ((lane >> 4) & 1) * 8;   // +8 cols for matrices 2,3
    uint32_t a_off[4][2], b_off[2][2];
#pragma unroll
    for (int mt = 0; mt < 4; mt++)
#pragma unroll
        for (int g = 0; g < 2; g++)
            a_off[mt][g] = ((wm * 64 + mt * 16 + l8 + rplus) * HS + g * 16 + cplus) * 2;
#pragma unroll
    for (int p = 0; p < 2; p++)
#pragma unroll
        for (int g = 0; g < 2; g++)
            b_off[p][g] = B_OFF + ((wn * 32 + p * 16 + l8 + rplus) * HS + g * 16 + cplus) * 2;

    auto issue = [&](int kt) {
        uint32_t sb = smbase + (kt % NSTAGE) * STAGE_BYTES;
        int k0 = kt * TK;
#pragma unroll
        for (int i = 0; i < 2; i++) {
            int r = lrow + i * 64;
            const __half* src = A + (long)(m0 + r) * lda + k0 + lc8;
            uint32_t dst = sb + (r * HS + lc8) * 2;
            asm volatile("cp.async.cg.shared.global [%0], [%1], 16;" :: "r"(dst), "l"(src));
        }
#pragma unroll
        for (int i = 0; i < 2; i++) {
            int r = lrow + i * 64;
            int n = n0 + r;
            int sz = (n < N) ? 16 : 0;
            const __half* src = Bt + (sz ? ((long)n * K + k0 + lc8) : 0);
            uint32_t dst = sb + B_OFF + (r * HS + lc8) * 2;
            asm volatile("cp.async.cg.shared.global [%0], [%1], 16, %2;"
                         :: "r"(dst), "l"(src), "r"(sz));
        }
        asm volatile("cp.async.commit_group;");
    };

    float c[4][4][4];
#pragma unroll
    for (int i = 0; i < 4; i++)
#pragma unroll
        for (int j = 0; j < 4; j++)
#pragma unroll
            for (int k = 0; k < 4; k++) c[i][j][k] = 0.f;

    issue(0);
    issue(1);
    for (int kt = 0; kt < nk; kt++) {
        if (kt + 2 < nk) {
            issue(kt + 2);
            asm volatile("cp.async.wait_group 2;");
        } else if (kt + 1 < nk) {
            asm volatile("cp.async.wait_group 1;");
        } else {
            asm volatile("cp.async.wait_group 0;");
        }
        __syncthreads();
        uint32_t sb = smbase + (kt % NSTAGE) * STAGE_BYTES;
#pragma unroll
        for (int g = 0; g < 2; g++) {
            uint32_t a[4][4], bf[2][4];
#pragma unroll
            for (int mt = 0; mt < 4; mt++) LDSM_X4(a[mt], sb + a_off[mt][g]);
#pragma unroll
            for (int p = 0; p < 2; p++) LDSM_X4(bf[p], sb + b_off[p][g]);
#pragma unroll
            for (int mt = 0; mt < 4; mt++)
#pragma unroll
                for (int nt = 0; nt < 4; nt++) {
                    uint32_t b0 = bf[nt >> 1][nt & 1];
                    uint32_t b1 = bf[nt >> 1][2 + (nt & 1)];
                    MMA_F16(c[mt][nt], a[mt][0], a[mt][1], a[mt][2], a[mt][3], b0, b1);
                }
        }
        __syncthreads();
    }

#pragma unroll
    for (int mt = 0; mt < 4; mt++) {
        int r0 = m0 + wm * 64 + mt * 16 + gid;
#pragma unroll
        for (int nt = 0; nt < 4; nt++) {
            int col = n0 + wn * 32 + nt * 8 + tid4 * 2;
            if (col < N) {
                float b0 = bias[col], b1 = bias[col + 1];
                float v00 = epi(c[mt][nt][0], b0, act);
                float v01 = epi(c[mt][nt][1], b1, act);
                float v10 = epi(c[mt][nt][2], b0, act);
                float v11 = epi(c[mt][nt][3], b1, act);
                if (outmode & 1) {
                    float2 u0; u0.x = v00; u0.y = v01;
                    float2 u1; u1.x = v10; u1.y = v11;
                    *(float2*)&C32[(long)r0 * N + col] = u0;
                    *(float2*)&C32[(long)(r0 + 8) * N + col] = u1;
                }
                if (outmode & 2) {
                    *(__half2*)&C16[(long)r0 * N + col] = __floats2half2_rn(v00, v01);
                    *(__half2*)&C16[(long)(r0 + 8) * N + col] = __floats2half2_rn(v10, v11);
                }
            }
        }
    }
}

// ---------------- flash attention (tf32 MMA) ---------------------------------
#define AT_QS 36
#define AT_KS 36
#define AT_VS 40
#define SM_SCALE 0.17677669529663687f

__global__ __launch_bounds__(128)
void flash_attn(const float* __restrict__ QK, const float* __restrict__ Vm,
                __half* __restrict__ O) {
    __shared__ float Qs[64 * AT_QS];
    __shared__ float Ks[64 * AT_KS];
    __shared__ float Vs[64 * AT_VS];
    int t = threadIdx.x;
    int lane = t & 31, w = t >> 5;
    int gid = lane >> 2, tid4 = lane & 3;
    int qt = blockIdx.x;
    int bh = blockIdx.y;
    int b = bh >> 3, h = bh & 7;
    long rowbase = (long)b * QLEN;

#pragma unroll
    for (int i = 0; i < 4; i++) {
        int e = t + i * 128;
        int row = e >> 3, c4 = (e & 7) * 4;
        int q = qt * 64 + row;
        float4 v = make_float4(0.f, 0.f, 0.f, 0.f);
        if (q < QLEN) v = *(const float4*)&QK[(rowbase + q) * 512 + h * HD + c4];
        *(float4*)&Qs[row * AT_QS + c4] = v;
    }
    __syncthreads();

    uint32_t aq[4][4];
    int r0 = w * 16 + gid;
#pragma unroll
    for (int k4 = 0; k4 < 4; k4++) {
        int ks = k4 * 8;
        aq[k4][0] = f2tf(Qs[r0 * AT_QS + ks + tid4]);
        aq[k4][1] = f2tf(Qs[(r0 + 8) * AT_QS + ks + tid4]);
        aq[k4][2] = f2tf(Qs[r0 * AT_QS + ks + tid4 + 4]);
        aq[k4][3] = f2tf(Qs[(r0 + 8) * AT_QS + ks + tid4 + 4]);
    }

    float m0 = -1e30f, m1 = -1e30f, l0 = 0.f, l1 = 0.f;
    float co[4][4] = {};

    for (int kt = 0; kt < 5; kt++) {
        __syncthreads();
#pragma unroll
        for (int i = 0; i < 4; i++) {
            int e = t + i * 128;
            int row = e >> 3, c4 = (e & 7) * 4;
            int kk = kt * 64 + row;
            float4 v = make_float4(0.f, 0.f, 0.f, 0.f);
            float4 u = make_float4(0.f, 0.f, 0.f, 0.f);
            if (kk < QLEN) {
                v = *(const float4*)&QK[(rowbase + kk) * 512 + 256 + h * HD + c4];
                u = *(const float4*)&Vm[(rowbase + kk) * 256 + h * HD + c4];
            }
            *(float4*)&Ks[row * AT_KS + c4] = v;
            *(float4*)&Vs[row * AT_VS + c4] = u;
        }
        __syncthreads();

        float cs[8][4];
#pragma unroll
        for (int nt = 0; nt < 8; nt++)
#pragma unroll
            for (int j = 0; j < 4; j++) cs[nt][j] = 0.f;
#pragma unroll
        for (int k4 = 0; k4 < 4; k4++) {
            int ks = k4 * 8;
#pragma unroll
            for (int nt = 0; nt < 8; nt++) {
                int key = nt * 8 + gid;
                uint32_t b0 = f2tf(Ks[key * AT_KS + ks + tid4]);
                uint32_t b1 = f2tf(Ks[key * AT_KS + ks + tid4 + 4]);
                MMA_TF32(cs[nt], aq[k4][0], aq[k4][1], aq[k4][2], aq[k4][3], b0, b1);
            }
        }

#pragma unroll
        for (int nt = 0; nt < 8; nt++)
#pragma unroll
            for (int j = 0; j < 4; j++) cs[nt][j] *= SM_SCALE;

        if (kt == 4) {
#pragma unroll
            for (int nt = 0; nt < 8; nt++) {
                int col = 256 + nt * 8 + 2 * tid4;
                if (col >= QLEN)     { cs[nt][0] = -1e30f; cs[nt][2] = -1e30f; }
                if (col + 1 >= QLEN) { cs[nt][1] = -1e30f; cs[nt][3] = -1e30f; }
            }
        }

        float t0 = -1e30f, t1 = -1e30f;
#pragma unroll
        for (int nt = 0; nt < 8; nt++) {
            t0 = fmaxf(t0, fmaxf(cs[nt][0], cs[nt][1]));
            t1 = fmaxf(t1, fmaxf(cs[nt][2], cs[nt][3]));
        }
#pragma unroll
        for (int off = 1; off <= 2; off <<= 1) {
            t0 = fmaxf(t0, __shfl_xor_sync(0xffffffffu, t0, off));
            t1 = fmaxf(t1, __shfl_xor_sync(0xffffffffu, t1, off));
        }
        float nm0 = fmaxf(m0, t0), nm1 = fmaxf(m1, t1);
        float sc0 = __expf(m0 - nm0), sc1 = __expf(m1 - nm1);
        m0 = nm0; m1 = nm1;

        float s0 = 0.f, s1 = 0.f;
#pragma unroll
        for (int nt = 0; nt < 8; nt++) {
            cs[nt][0] = __expf(cs[nt][0] - nm0);
            cs[nt][1] = __expf(cs[nt][1] - nm0);
            cs[nt][2] = __expf(cs[nt][2] - nm1);
            cs[nt][3] = __expf(cs[nt][3] - nm1);
            s0 += cs[nt][0] + cs[nt][1];
            s1 += cs[nt][2] + cs[nt][3];
        }
#pragma unroll
        for (int off = 1; off <= 2; off <<= 1) {
            s0 += __shfl_xor_sync(0xffffffffu, s0, off);
            s1 += __shfl_xor_sync(0xffffffffu, s1, off);
        }
        l0 = l0 * sc0 + s0;
        l1 = l1 * sc1 + s1;
#pragma unroll
        for (int dt = 0; dt < 4; dt++) {
            co[dt][0] *= sc0; co[dt][1] *= sc0;
            co[dt][2] *= sc1; co[dt][3] *= sc1;
        }

        int L1 = (gid << 2) | (tid4 >> 1);
        int L2 = L1 + 2;
        bool odd = tid4 & 1;
#pragma unroll
        for (int kk = 0; kk < 8; kk++) {
            float p00 = __shfl_sync(0xffffffffu, cs[kk][0], L1);
            float p01 = __shfl_sync(0xffffffffu, cs[kk][1], L1);
            float p10 = __shfl_sync(0xffffffffu, cs[kk][2], L1);
            float p11 = __shfl_sync(0xffffffffu, cs[kk][3], L1);
            float q00 = __shfl_sync(0xffffffffu, cs[kk][0], L2);
            float q01 = __shfl_sync(0xffffffffu, cs[kk][1], L2);
            float q10 = __shfl_sync(0xffffffffu, cs[kk][2], L2);
            float q11 = __shfl_sync(0xffffffffu, cs[kk][3], L2);
            uint32_t a0 = f2tf(odd ? p01 : p00);
            uint32_t a1 = f2tf(odd ? p11 : p10);
            uint32_t a2 = f2tf(odd ? q01 : q00);
            uint32_t a3 = f2tf(odd ? q11 : q10);
#pragma unroll
            for (int dt = 0; dt < 4; dt++) {
                int d = dt * 8 + gid;
                uint32_t b0 = f2tf(Vs[(kk * 8 + tid4) * AT_VS + d]);
                uint32_t b1 = f2tf(Vs[(kk * 8 + tid4 + 4) * AT_VS + d]);
                MMA_TF32(co[dt], a0, a1, a2, a3, b0, b1);
            }
        }
    }

    float il0 = 1.f / l0, il1 = 1.f / l1;
    int q0 = qt * 64 + w * 16 + gid;
    int q1 = q0 + 8;
#pragma unroll
    for (int dt = 0; dt < 4; dt++) {
        int d = h * HD + dt * 8 + 2 * tid4;
        if (q0 < QLEN)
            *(__half2*)&O[((long)b * QLEN + q0) * D + d] =
                __floats2half2_rn(co[dt][0] * il0, co[dt][1] * il0);
        if (q1 < QLEN)
            *(__half2*)&O[((long)b * QLEN + q1) * D + d] =
                __floats2half2_rn(co[dt][2] * il1, co[dt][3] * il1);
    }
}

// ---------------- layernorm ----------------------------------------------------
__device__ __forceinline__ float block_sum256(float v) {
    __shared__ float sh[8];
#pragma unroll
    for (int off = 16; off > 0; off >>= 1)
        v += __shfl_xor_sync(0xffffffffu, v, off);
    int t = threadIdx.x;
    if ((t & 31) == 0) sh[t >> 5] = v;
    __syncthreads();
    if (t == 0) {
        float s = 0.f;
        for (int i = 0; i < 8; i++) s += sh[i];
        sh[0] = s;
    }
    __syncthreads();
    float r = sh[0];
    __syncthreads();
    return r;
}

__device__ __forceinline__ void ln_write(float x, const float* w, const float* bb,
                                         float* O32, __half* O16, int stride16, int row) {
    int t = threadIdx.x;
    float mean = block_sum256(x) * (1.f / D);
    float d_ = x - mean;
    float var = block_sum256(d_ * d_) * (1.f / D);
    float y = d_ * rsqrtf(var + LN_EPS) * w[t] + bb[t];
    O32[(long)row * D + t] = y;
    if (O16) O16[(long)row * stride16 + t] = __float2half_rn(y);
}

__global__ void ln_add(const float* __restrict__ A, const float* __restrict__ Bv,
                       const float* __restrict__ w, const float* __restrict__ bb,
                       float* __restrict__ O32, __half* O16, int stride16) {
    int row = blockIdx.x, t = threadIdx.x;
    float x = A[(long)row * D + t] + Bv[(long)row * D + t];
    ln_write(x, w, bb, O32, O16, stride16, row);
}

__global__ void gate_ln(const float* __restrict__ gates, const float* __restrict__ res,
                        const float* __restrict__ ca, const float* __restrict__ w,
                        const float* __restrict__ bb, float* __restrict__ O32,
                        __half* O16) {
    int row = blockIdx.x, t = threadIdx.x;
    float g1 = gates[(long)row * 512 + t];
    float g2 = gates[(long)row * 512 + 256 + t];
    float x = g1 * res[(long)row * D + t] + g2 * ca[(long)row * D + t];
    ln_write(x, w, bb, O32, O16, 256, row);
}

// ---------------- deformable sampling + fused softmax -------------------------
__global__ void sample_kernel(const float* __restrict__ enc, const float* __restrict__ ref,
                              const float* __restrict__ offaw, float* __restrict__ ca,
                              __half* __restrict__ cat16) {
    int bq = blockIdx.x;
    int b = bq / QLEN;
    int t = threadIdx.x;
    int h = t >> 5, lane = t & 31;
    const float* rp = ref + (long)bq * 4;
    float rx = rp[0], ry = rp[1], rw = rp[2], rh = rp[3];
    const float* op = offaw + (long)bq * 288 + h * 24;
    const float* lp = offaw + (long)bq * 288 + 192 + h * SP;
    const float* eb = enc + (long)b * S_TOT * D + h * HD + lane;

    float lg[SP];
    float mx = -1e30f;
#pragma unroll
    for (int i = 0; i < SP; i++) { lg[i] = lp[i]; mx = fmaxf(mx, lg[i]); }
    float ssum = 0.f;
#pragma unroll
    for (int i = 0; i < SP; i++) { lg[i] = __expf(lg[i] - mx); ssum += lg[i]; }
    float inv = 1.f / ssum;

    float acc = 0.f;
#pragma unroll
    for (int p = 0; p < SP; p++) {
        int lvl = p >> 2;
        int Wl = (lvl == 0) ? 80 : (lvl == 1) ? 40 : 20;
        int s0 = (lvl == 0) ? 0 : (lvl == 1) ? 6400 : 8000;
        float ox = op[p * 2], oy = op[p * 2 + 1];
        float a = lg[p] * inv;
        float gx = (rx + ox * 0.125f * rw) * (float)Wl - 0.5f;
        float gy = (ry + oy * 0.125f * rh) * (float)Wl - 0.5f;
        float x0f = floorf(gx), y0f = floorf(gy);
        float fx = gx - x0f, fy = gy - y0f;
        int x0 = (int)x0f, y0 = (int)y0f;
        int x1 = x0 + 1, y1 = y0 + 1;
        float vx0 = (x0 >= 0 && x0 < Wl) ? 1.f : 0.f;
        float vx1 = (x1 >= 0 && x1 < Wl) ? 1.f : 0.f;
        float vy0 = (y0 >= 0 && y0 < Wl) ? 1.f : 0.f;
        float vy1 = (y1 >= 0 && y1 < Wl) ? 1.f : 0.f;
        float w00 = (1.f - fx) * (1.f - fy) * a * vx0 * vy0;
        float w10 = fx * (1.f - fy) * a * vx1 * vy0;
        float w01 = (1.f - fx) * fy * a * vx0 * vy1;
        float w11 = fx * fy * a * vx1 * vy1;
        int xc0 = min(max(x0, 0), Wl - 1), xc1 = min(max(x1, 0), Wl - 1);
        int yc0 = min(max(y0, 0), Wl - 1), yc1 = min(max(y1, 0), Wl - 1);
        float e00 = eb[(long)(s0 + yc0 * Wl + xc0) * D];
        float e10 = eb[(long)(s0 + yc0 * Wl + xc1) * D];
        float e01 = eb[(long)(s0 + yc1 * Wl + xc0) * D];
        float e11 = eb[(long)(s0 + yc1 * Wl + xc1) * D];
        acc += w00 * e00 + w10 * e10 + w01 * e01 + w11 * e11;
    }
    ca[(long)bq * D + h * HD + lane] = acc;
    cat16[(long)bq * 512 + 256 + h * HD + lane] = __float2half_rn(acc);
}

// ---------------- host orchestration -----------------------------------------
static void launch_gemm(const __half* A, const __half* Bt, const float* bias,
                        float* C32, __half* C16, int M, int N, int K, int lda,
                        int act, int outmode) {
    dim3 grid((N + TN - 1) / TN, M / TM);
    tgemm_h<<<grid, 256, GSMEM>>>(A, Bt, bias, C32, C16, M, N, K, lda, act, outmode);
}

extern "C" void kernel_launch(void* const* d_in, const int* in_sizes, int n_in,
                              void* d_out, int out_size) {
    const float* hs    = (const float*)d_in[0];
    const float* pos   = (const float*)d_in[1];
    const float* ref   = (const float*)d_in[2];
    const float* enc   = (const float*)d_in[3];
    const float* q_w   = (const float*)d_in[4];
    const float* q_b   = (const float*)d_in[5];
    const float* k_w   = (const float*)d_in[6];
    const float* k_b   = (const float*)d_in[7];
    const float* v_w   = (const float*)d_in[8];
    const float* v_b   = (const float*)d_in[9];
    const float* o_w   = (const float*)d_in[10];
    const float* o_b   = (const float*)d_in[11];
    const float* sa_ln_w = (const float*)d_in[12];
    const float* sa_ln_b = (const float*)d_in[13];
    const float* off_w = (const float*)d_in[14];
    const float* off_b = (const float*)d_in[15];
    const float* aw_w  = (const float*)d_in[16];
    const float* aw_b  = (const float*)d_in[17];
    const float* gate_w = (const float*)d_in[18];
    const float* gate_b = (const float*)d_in[19];
    const float* gate_ln_w = (const float*)d_in[20];
    const float* gate_ln_b = (const float*)d_in[21];
    const float* fc1_w = (const float*)d_in[22];
    const float* fc1_b = (const float*)d_in[23];
    const float* fc2_w = (const float*)d_in[24];
    const float* fc2_b = (const float*)d_in[25];
    const float* fin_ln_w = (const float*)d_in[26];
    const float* fin_ln_b = (const float*)d_in[27];
    float* out = (float*)d_out;

    __half *p_hq16, *p_hs16, *p_attn16, *p_cat16, *p_h216, *p_ffn1, *p_wt;
    float *p_qk, *p_v, *p_res, *p_offaw, *p_ca, *p_gates, *p_h2, *p_ffn2,
          *p_qkb, *p_oab;
    cudaGetSymbolAddress((void**)&p_hq16, g_hq16);
    cudaGetSymbolAddress((void**)&p_hs16, g_hs16);
    cudaGetSymbolAddress((void**)&p_qk, g_qk);
    cudaGetSymbolAddress((void**)&p_v, g_v);
    cudaGetSymbolAddress((void**)&p_attn16, g_attn16);
    cudaGetSymbolAddress((void**)&p_res, g_res);
    cudaGetSymbolAddress((void**)&p_offaw, g_offaw);
    cudaGetSymbolAddress((void**)&p_ca, g_ca);
    cudaGetSymbolAddress((void**)&p_cat16, g_cat16);
    cudaGetSymbolAddress((void**)&p_gates, g_gates);
    cudaGetSymbolAddress((void**)&p_h2, g_h2);
    cudaGetSymbolAddress((void**)&p_h216, g_h216);
    cudaGetSymbolAddress((void**)&p_ffn1, g_ffn1);
    cudaGetSymbolAddress((void**)&p_ffn2, g_ffn2);
    cudaGetSymbolAddress((void**)&p_wt, g_wt16);
    cudaGetSymbolAddress((void**)&p_qkb, g_qkb);
    cudaGetSymbolAddress((void**)&p_oab, g_oab);

    cudaFuncSetAttribute(tgemm_h, cudaFuncAttributeMaxDynamicSharedMemorySize, GSMEM);

    dim3 blk(256);

    TWArgs tw;
    tw.src[0] = q_w;  tw.src[1] = k_w;   tw.src[2] = v_w;  tw.src[3] = o_w;
    tw.src[4] = off_w; tw.src[5] = aw_w; tw.src[6] = gate_w;
    tw.src[7] = fc1_w; tw.src[8] = fc2_w;
    transpose_all<<<1096, dim3(32, 8)>>>(tw, p_wt);
    bias_fuse<<<4, 256>>>(q_b, k_b, off_b, aw_b, p_qkb, p_oab);

    prep_kernel<<<BQ * D / 256, blk>>>(hs, pos, p_hq16, p_hs16, BQ * D);

    launch_gemm(p_hq16, p_wt + WT_QK, p_qkb, p_qk, nullptr, BQ, 512, D, 256, 0, 1);
    launch_gemm(p_hs16, p_wt + WT_V,  v_b,   p_v,  nullptr, BQ, 256, D, 256, 0, 1);

    flash_attn<<<dim3(5, BATCH * NH), 128>>>(p_qk, p_v, p_attn16);

    launch_gemm(p_attn16, p_wt + WT_O, o_b, p_qk, nullptr, BQ, 256, D, 256, 0, 1);
    ln_add<<<BQ, blk>>>(hs, p_qk, sa_ln_w, sa_ln_b, p_res, p_cat16, 512);

    launch_gemm(p_cat16, p_wt + WT_OA, p_oab, p_offaw, nullptr, BQ, 288, D, 512, 0, 1);

    sample_kernel<<<BQ, blk>>>(enc, ref, p_offaw, p_ca, p_cat16);

    launch_gemm(p_cat16, p_wt + WT_GATE, gate_b, p_gates, nullptr, BQ, 512, 512, 512, 2, 1);
    gate_ln<<<BQ, blk>>>(p_gates, p_res, p_ca, gate_ln_w, gate_ln_b, p_h2, p_h216);

    launch_gemm(p_h216, p_wt + WT_FC1, fc1_b, nullptr, p_ffn1, BQ, FF, D, 256, 1, 2);
    launch_gemm(p_ffn1, p_wt + WT_FC2, fc2_b, p_ffn2, nullptr, BQ, 256, FF, 1024, 0, 1);

    ln_add<<<BQ, blk>>>(p_h2, p_ffn2, fin_ln_w, fin_ln_b, out, nullptr, 0);
}